// round 2
// baseline (speedup 1.0000x reference)
#include <cuda_runtime.h>

#define NU 100000
#define NP 50000
#define NN 150000   // NU + NP
#define NE 250000
#define D  256

// ---------------- scratch (static device globals; no allocation) ----------------
__device__ float g_x[(size_t)NN * D];   // node features / conv output
__device__ float g_h[(size_t)NN * D];   // x @ W  (also reused for MLP node-partials)
__device__ float g_dinv[NN];
__device__ int   g_deg[NN];

// ---------------- degree / normalization ----------------
__global__ void k_degree(const int* __restrict__ ei) {
    int e = blockIdx.x * blockDim.x + threadIdx.x;
    if (e < NE) {
        atomicAdd(&g_deg[ei[e]], 1);        // edge p->u : dst u
        atomicAdd(&g_deg[ei[NE + e]], 1);   // edge u->p : dst p
    }
}

__global__ void k_dinv() {
    int n = blockIdx.x * blockDim.x + threadIdx.x;
    if (n < NN) g_dinv[n] = rsqrtf((float)g_deg[n] + 1.0f);  // +1 self loop
}

// ---------------- generic tiled GEMM: C[M,256] = A[M,K] @ W[K,256] (+bias)(+emb) ----------------
// Tiles: 64x64x32, 256 threads, 4x4 microtile per thread.
__global__ void gemm64(const float* __restrict__ A,
                       const float* __restrict__ W,
                       const float* __restrict__ bias,
                       const float* __restrict__ emb,
                       float* __restrict__ C, int M, int K) {
    __shared__ float As[64][33];   // padded: conflict-free transposed-ish access
    __shared__ float Bs[32][64];

    int tid = threadIdx.x;
    int tx = tid & 15;      // column group (4 cols)
    int ty = tid >> 4;      // row group    (4 rows)
    int rowBase = blockIdx.x * 64;
    int colBase = blockIdx.y * 64;

    float acc[4][4] = {};

    for (int k0 = 0; k0 < K; k0 += 32) {
        // load A tile 64x32 (512 float4, 2 per thread)
        #pragma unroll
        for (int i = 0; i < 2; i++) {
            int lin = tid + i * 256;
            int r  = lin >> 3;
            int c4 = lin & 7;
            float4 v = make_float4(0.f, 0.f, 0.f, 0.f);
            int gr = rowBase + r;
            if (gr < M) v = *(const float4*)&A[(size_t)gr * K + k0 + c4 * 4];
            As[r][c4 * 4 + 0] = v.x;
            As[r][c4 * 4 + 1] = v.y;
            As[r][c4 * 4 + 2] = v.z;
            As[r][c4 * 4 + 3] = v.w;
        }
        // load W tile 32x64
        #pragma unroll
        for (int i = 0; i < 2; i++) {
            int lin = tid + i * 256;
            int r  = lin >> 4;
            int c4 = lin & 15;
            *(float4*)&Bs[r][c4 * 4] =
                *(const float4*)&W[(size_t)(k0 + r) * 256 + colBase + c4 * 4];
        }
        __syncthreads();

        #pragma unroll
        for (int kk = 0; kk < 32; kk++) {
            float4 b = *(const float4*)&Bs[kk][tx * 4];
            float a0 = As[ty * 4 + 0][kk];
            float a1 = As[ty * 4 + 1][kk];
            float a2 = As[ty * 4 + 2][kk];
            float a3 = As[ty * 4 + 3][kk];
            acc[0][0] += a0 * b.x; acc[0][1] += a0 * b.y; acc[0][2] += a0 * b.z; acc[0][3] += a0 * b.w;
            acc[1][0] += a1 * b.x; acc[1][1] += a1 * b.y; acc[1][2] += a1 * b.z; acc[1][3] += a1 * b.w;
            acc[2][0] += a2 * b.x; acc[2][1] += a2 * b.y; acc[2][2] += a2 * b.z; acc[2][3] += a2 * b.w;
            acc[3][0] += a3 * b.x; acc[3][1] += a3 * b.y; acc[3][2] += a3 * b.z; acc[3][3] += a3 * b.w;
        }
        __syncthreads();
    }

    // epilogue
    #pragma unroll
    for (int i = 0; i < 4; i++) {
        int gr = rowBase + ty * 4 + i;
        if (gr >= M) continue;
        int gc = colBase + tx * 4;
        float4 v = make_float4(acc[i][0], acc[i][1], acc[i][2], acc[i][3]);
        if (bias) {
            float4 bb = *(const float4*)&bias[gc];
            v.x += bb.x; v.y += bb.y; v.z += bb.z; v.w += bb.w;
        }
        if (emb) {
            float4 ee = *(const float4*)&emb[(size_t)gr * 256 + gc];
            v.x += ee.x; v.y += ee.y; v.z += ee.z; v.w += ee.w;
        }
        *(float4*)&C[(size_t)gr * 256 + gc] = v;
    }
}

// ---------------- GCN aggregation ----------------
// self-loop init: g_x = dinv[n]^2 * g_h
__global__ void k_selfinit() {
    int i = blockIdx.x * blockDim.x + threadIdx.x;
    if (i >= NN * 64) return;
    int n = i >> 6;
    float di = g_dinv[n];
    float s = di * di;
    float4 h = ((const float4*)g_h)[i];
    ((float4*)g_x)[i] = make_float4(h.x * s, h.y * s, h.z * s, h.w * s);
}

// edge scatter: both directions, symmetric norm
__global__ void k_scatter(const int* __restrict__ ei) {
    int i = blockIdx.x * blockDim.x + threadIdx.x;
    if (i >= NE * 64) return;
    int e = i >> 6;
    int c = (i & 63) << 2;
    int u = ei[e];
    int p = ei[NE + e];
    float nrm = g_dinv[u] * g_dinv[p];
    float4 hu = *(const float4*)&g_h[(size_t)u * D + c];
    float4 hp = *(const float4*)&g_h[(size_t)p * D + c];
    float* yu = &g_x[(size_t)u * D + c];
    float* yp = &g_x[(size_t)p * D + c];
    atomicAdd(yp + 0, hu.x * nrm);
    atomicAdd(yp + 1, hu.y * nrm);
    atomicAdd(yp + 2, hu.z * nrm);
    atomicAdd(yp + 3, hu.w * nrm);
    atomicAdd(yu + 0, hp.x * nrm);
    atomicAdd(yu + 1, hp.y * nrm);
    atomicAdd(yu + 2, hp.z * nrm);
    atomicAdd(yu + 3, hp.w * nrm);
}

// bias + optional relu (in place on g_x)
__global__ void k_finish(const float* __restrict__ b, int relu) {
    int i = blockIdx.x * blockDim.x + threadIdx.x;
    if (i >= NN * 64) return;
    int c = (i & 63) << 2;
    float4 v = ((const float4*)g_x)[i];
    float4 bb = *(const float4*)&b[c];
    v.x += bb.x; v.y += bb.y; v.z += bb.z; v.w += bb.w;
    if (relu) {
        v.x = fmaxf(v.x, 0.f); v.y = fmaxf(v.y, 0.f);
        v.z = fmaxf(v.z, 0.f); v.w = fmaxf(v.w, 0.f);
    }
    ((float4*)g_x)[i] = v;
}

// ---------------- per-edge MLP epilogue ----------------
// g_h holds node partials: rows [0,NU) = x_u @ m1W_top, rows [NU,NN) = x_p @ m1W_bot.
// pred[e] = relu(g_h[u] + g_h[p] + m1b) . m2W + m2b        (one warp per edge)
__global__ void k_edge_pred(const int* __restrict__ ei,
                            const float* __restrict__ m1b,
                            const float* __restrict__ m2W,
                            const float* __restrict__ m2b,
                            float* __restrict__ out) {
    int gid = blockIdx.x * blockDim.x + threadIdx.x;
    int w = gid >> 5;
    int lane = gid & 31;
    if (w >= NE) return;
    int u = ei[w];
    int p = ei[NE + w];   // global product node index -> row NU + local
    const float4* b1 = (const float4*)&g_h[(size_t)u * D];
    const float4* b2 = (const float4*)&g_h[(size_t)p * D];
    const float4* bias4 = (const float4*)m1b;
    const float4* w4 = (const float4*)m2W;
    float s = 0.f;
    #pragma unroll
    for (int i = 0; i < 2; i++) {
        int idx = lane + 32 * i;
        float4 a = b1[idx];
        float4 b = b2[idx];
        float4 bb = bias4[idx];
        float4 ww = w4[idx];
        float h0 = fmaxf(a.x + b.x + bb.x, 0.f);
        float h1 = fmaxf(a.y + b.y + bb.y, 0.f);
        float h2 = fmaxf(a.z + b.z + bb.z, 0.f);
        float h3 = fmaxf(a.w + b.w + bb.w, 0.f);
        s += h0 * ww.x + h1 * ww.y + h2 * ww.z + h3 * ww.w;
    }
    #pragma unroll
    for (int o = 16; o; o >>= 1) s += __shfl_down_sync(0xFFFFFFFFu, s, o);
    if (lane == 0) out[w] = s + m2b[0];
}

// ---------------- launch ----------------
extern "C" void kernel_launch(void* const* d_in, const int* in_sizes, int n_in,
                              void* d_out, int out_size) {
    const int*   ei   = (const int*)d_in[0];
    const float* uf   = (const float*)d_in[1];
    const float* pf   = (const float*)d_in[2];
    const float* uemb = (const float*)d_in[3];
    const float* pemb = (const float*)d_in[4];
    const float* uW   = (const float*)d_in[5];
    const float* ub   = (const float*)d_in[6];
    const float* pW   = (const float*)d_in[7];
    const float* pb   = (const float*)d_in[8];
    const float* c1W  = (const float*)d_in[9];
    const float* c1b  = (const float*)d_in[10];
    const float* c2W  = (const float*)d_in[11];
    const float* c2b  = (const float*)d_in[12];
    const float* m1W  = (const float*)d_in[13];
    const float* m1b  = (const float*)d_in[14];
    const float* m2W  = (const float*)d_in[15];
    const float* m2b  = (const float*)d_in[16];
    float* preds = (float*)d_out;

    float* xp;  float* hp;  int* degp;
    cudaGetSymbolAddress((void**)&xp, g_x);
    cudaGetSymbolAddress((void**)&hp, g_h);
    cudaGetSymbolAddress((void**)&degp, g_deg);

    // degrees + normalization
    cudaMemsetAsync(degp, 0, NN * sizeof(int), 0);
    k_degree<<<(NE + 255) / 256, 256>>>(ei);
    k_dinv<<<(NN + 255) / 256, 256>>>();

    dim3 gU((NU + 63) / 64, 4);
    dim3 gP((NP + 63) / 64, 4);
    dim3 gN((NN + 63) / 64, 4);

    // input transforms: x = feats @ W + b + emb
    gemm64<<<gU, 256>>>(uf, uW, ub, uemb, xp, NU, 128);
    gemm64<<<gP, 256>>>(pf, pW, pb, pemb, xp + (size_t)NU * D, NP, 128);

    const int nElem = (NN * 64 + 255) / 256;
    const int nScat = (NE * 64 + 255) / 256;

    // conv1 (relu)
    gemm64<<<gN, 256>>>(xp, c1W, nullptr, nullptr, hp, NN, 256);
    k_selfinit<<<nElem, 256>>>();
    k_scatter<<<nScat, 256>>>(ei);
    k_finish<<<nElem, 256>>>(c1b, 1);

    // conv2 (no relu)
    gemm64<<<gN, 256>>>(xp, c2W, nullptr, nullptr, hp, NN, 256);
    k_selfinit<<<nElem, 256>>>();
    k_scatter<<<nScat, 256>>>(ei);
    k_finish<<<nElem, 256>>>(c2b, 0);

    // MLP factored through nodes:
    // g_h[0:NU)   = x_users @ m1W[0:256]
    // g_h[NU:NN)  = x_prods @ m1W[256:512]
    gemm64<<<gU, 256>>>(xp, m1W, nullptr, nullptr, hp, NU, 256);
    gemm64<<<gP, 256>>>(xp + (size_t)NU * D, m1W + 256 * 256, nullptr, nullptr,
                        hp + (size_t)NU * D, NP, 256);

    // per-edge scoring
    k_edge_pred<<<(NE * 32 + 255) / 256, 256>>>(ei, m1b, m2W, m2b, preds);
}

// round 3
// speedup vs baseline: 1.0889x; 1.0889x over previous
#include <cuda_runtime.h>

#define NU 100000
#define NP 50000
#define NN 150000   // NU + NP
#define NE 250000
#define D  256

// ---------------- scratch (static device globals; no allocation) ----------------
__device__ float g_x[(size_t)NN * D];   // node features / conv output
__device__ float g_h[(size_t)NN * D];   // x @ W  (also MLP node-partials)
__device__ float g_dinv[NN];
__device__ int   g_deg[NN];
__device__ int   g_off[NN];
__device__ int   g_cur[NN];
__device__ int   g_total;
__device__ int   g_adj[2 * NE];         // src node id per CSR slot
__device__ float g_adn[2 * NE];         // dinv[src] per CSR slot

// ---------------- degree / normalization ----------------
__global__ void k_degree(const int* __restrict__ ei) {
    int e = blockIdx.x * blockDim.x + threadIdx.x;
    if (e < NE) {
        atomicAdd(&g_deg[ei[e]], 1);
        atomicAdd(&g_deg[ei[NE + e]], 1);
    }
}

__global__ void k_dinv() {
    int n = blockIdx.x * blockDim.x + threadIdx.x;
    if (n < NN) g_dinv[n] = rsqrtf((float)g_deg[n] + 1.0f);  // +1 self loop
}

// warp-aggregated offset allocation: ~4.7k atomics on g_total instead of 150k
__global__ void k_offsets() {
    int n = blockIdx.x * blockDim.x + threadIdx.x;
    int lane = threadIdx.x & 31;
    int d = (n < NN) ? g_deg[n] : 0;
    // inclusive warp scan
    int incl = d;
    #pragma unroll
    for (int o = 1; o < 32; o <<= 1) {
        int t = __shfl_up_sync(0xFFFFFFFFu, incl, o);
        if (lane >= o) incl += t;
    }
    int excl = incl - d;
    int base = 0;
    if (lane == 31) base = atomicAdd(&g_total, incl);
    base = __shfl_sync(0xFFFFFFFFu, base, 31);
    if (n < NN) g_off[n] = base + excl;
}

__global__ void k_fill(const int* __restrict__ ei) {
    int e = blockIdx.x * blockDim.x + threadIdx.x;
    if (e >= NE) return;
    int u = ei[e];
    int p = ei[NE + e];
    float du = g_dinv[u], dp = g_dinv[p];
    int pos = atomicAdd(&g_cur[p], 1);
    int idx = g_off[p] + pos;
    g_adj[idx] = u;  g_adn[idx] = du;
    int pos2 = atomicAdd(&g_cur[u], 1);
    int idx2 = g_off[u] + pos2;
    g_adj[idx2] = p; g_adn[idx2] = dp;
}

// ---------------- GEMM: C[M,256] = A[M,K] @ W[K,256] (+bias)(+emb) ----------------
// 128x128 tile, K-step 16, 256 threads, 8x8 microtile (4+4 interleaved frags),
// smem double-buffered, one __syncthreads per K-step.
__global__ __launch_bounds__(256) void gemm128(const float* __restrict__ A,
                                               const float* __restrict__ W,
                                               const float* __restrict__ bias,
                                               const float* __restrict__ emb,
                                               float* __restrict__ C,
                                               int M, int K) {
    __shared__ float As[2][16][132];   // [k][m], padded
    __shared__ float Bs[2][16][128];   // [k][n]

    int tid = threadIdx.x;
    int tx = tid & 15;       // 16 col groups
    int ty = tid >> 4;       // 16 row groups
    int rowBase = blockIdx.x * 128;
    int colBase = blockIdx.y * 128;

    float acc[8][8];
    #pragma unroll
    for (int i = 0; i < 8; i++)
        #pragma unroll
        for (int j = 0; j < 8; j++) acc[i][j] = 0.f;

    float4 ra[2], rb[2];

    // ---- loaders ----
    #define LDA(k0)                                                              \
        {                                                                        \
            _Pragma("unroll")                                                    \
            for (int i = 0; i < 2; i++) {                                        \
                int lin = tid + i * 256;                                         \
                int r = lin >> 2, c4 = lin & 3;                                  \
                int gr = rowBase + r;                                            \
                ra[i] = (gr < M)                                                 \
                    ? *(const float4*)&A[(size_t)gr * K + (k0) + c4 * 4]         \
                    : make_float4(0.f, 0.f, 0.f, 0.f);                           \
            }                                                                    \
        }
    #define LDB(k0)                                                              \
        {                                                                        \
            _Pragma("unroll")                                                    \
            for (int i = 0; i < 2; i++) {                                        \
                int lin = tid + i * 256;                                         \
                int r = lin >> 5, c4 = lin & 31;                                 \
                rb[i] = *(const float4*)&W[(size_t)((k0) + r) * 256 + colBase + c4 * 4]; \
            }                                                                    \
        }
    #define STAB(b)                                                              \
        {                                                                        \
            _Pragma("unroll")                                                    \
            for (int i = 0; i < 2; i++) {                                        \
                int lin = tid + i * 256;                                         \
                int r = lin >> 2, c4 = lin & 3;                                  \
                As[b][c4 * 4 + 0][r] = ra[i].x;                                  \
                As[b][c4 * 4 + 1][r] = ra[i].y;                                  \
                As[b][c4 * 4 + 2][r] = ra[i].z;                                  \
                As[b][c4 * 4 + 3][r] = ra[i].w;                                  \
                int r2 = lin >> 5, c42 = lin & 31;                               \
                *(float4*)&Bs[b][r2][c42 * 4] = rb[i];                           \
            }                                                                    \
        }

    LDA(0); LDB(0); STAB(0);
    __syncthreads();

    int KT = K >> 4;
    int buf = 0;
    for (int kt = 0; kt < KT; kt++) {
        if (kt + 1 < KT) { LDA((kt + 1) << 4); LDB((kt + 1) << 4); }
        #pragma unroll
        for (int k = 0; k < 16; k++) {
            float4 a0 = *(const float4*)&As[buf][k][ty * 4];
            float4 a1 = *(const float4*)&As[buf][k][64 + ty * 4];
            float4 b0 = *(const float4*)&Bs[buf][k][tx * 4];
            float4 b1 = *(const float4*)&Bs[buf][k][64 + tx * 4];
            float av[8] = {a0.x, a0.y, a0.z, a0.w, a1.x, a1.y, a1.z, a1.w};
            float bv[8] = {b0.x, b0.y, b0.z, b0.w, b1.x, b1.y, b1.z, b1.w};
            #pragma unroll
            for (int i = 0; i < 8; i++)
                #pragma unroll
                for (int j = 0; j < 8; j++)
                    acc[i][j] += av[i] * bv[j];
        }
        if (kt + 1 < KT) {
            STAB(buf ^ 1);
            __syncthreads();
            buf ^= 1;
        }
    }

    // ---- epilogue ----
    #pragma unroll
    for (int i = 0; i < 8; i++) {
        int mr = (i < 4) ? (ty * 4 + i) : (64 + ty * 4 + (i - 4));
        int gr = rowBase + mr;
        if (gr >= M) continue;
        #pragma unroll
        for (int jh = 0; jh < 2; jh++) {
            int gc = colBase + jh * 64 + tx * 4;
            float4 v = make_float4(acc[i][jh * 4 + 0], acc[i][jh * 4 + 1],
                                   acc[i][jh * 4 + 2], acc[i][jh * 4 + 3]);
            if (bias) {
                float4 bb = *(const float4*)&bias[gc];
                v.x += bb.x; v.y += bb.y; v.z += bb.z; v.w += bb.w;
            }
            if (emb) {
                float4 ee = *(const float4*)&emb[(size_t)gr * 256 + gc];
                v.x += ee.x; v.y += ee.y; v.z += ee.z; v.w += ee.w;
            }
            *(float4*)&C[(size_t)gr * 256 + gc] = v;
        }
    }
    #undef LDA
    #undef LDB
    #undef STAB
}

// ---------------- fused GCN aggregation (CSR gather + self loop + bias + relu) --
// thread i handles node n = i>>6, cols [(i&63)*4, +4). One warp = one node.
__global__ void k_gather(const float* __restrict__ b, int relu) {
    int i = blockIdx.x * blockDim.x + threadIdx.x;
    if (i >= NN * 64) return;
    int n = i >> 6;
    int c = (i & 63) << 2;
    float di = g_dinv[n];
    float s2 = di * di;
    float4 h = *(const float4*)&g_h[(size_t)n * D + c];
    float4 acc = make_float4(h.x * s2, h.y * s2, h.z * s2, h.w * s2);
    int s0 = g_off[n];
    int s1 = s0 + g_deg[n];
    for (int j = s0; j < s1; j++) {
        int a = g_adj[j];                 // uniform across warp -> broadcast
        float nr = di * g_adn[j];
        float4 hv = *(const float4*)&g_h[(size_t)a * D + c];
        acc.x += hv.x * nr; acc.y += hv.y * nr;
        acc.z += hv.z * nr; acc.w += hv.w * nr;
    }
    float4 bb = *(const float4*)&b[c];
    acc.x += bb.x; acc.y += bb.y; acc.z += bb.z; acc.w += bb.w;
    if (relu) {
        acc.x = fmaxf(acc.x, 0.f); acc.y = fmaxf(acc.y, 0.f);
        acc.z = fmaxf(acc.z, 0.f); acc.w = fmaxf(acc.w, 0.f);
    }
    *(float4*)&g_x[(size_t)n * D + c] = acc;
}

// ---------------- per-edge MLP epilogue ----------------
// g_h rows [0,NU) = x_u @ m1W_top ; rows [NU,NN) = x_p @ m1W_bot.
// pred[e] = relu(g_h[u] + g_h[p] + m1b) . m2W + m2b    (one warp per edge)
__global__ void k_edge_pred(const int* __restrict__ ei,
                            const float* __restrict__ m1b,
                            const float* __restrict__ m2W,
                            const float* __restrict__ m2b,
                            float* __restrict__ out) {
    int gid = blockIdx.x * blockDim.x + threadIdx.x;
    int w = gid >> 5;
    int lane = gid & 31;
    if (w >= NE) return;
    int u = ei[w];
    int p = ei[NE + w];
    const float4* b1 = (const float4*)&g_h[(size_t)u * D];
    const float4* b2 = (const float4*)&g_h[(size_t)p * D];
    const float4* bias4 = (const float4*)m1b;
    const float4* w4 = (const float4*)m2W;
    float s = 0.f;
    #pragma unroll
    for (int i = 0; i < 2; i++) {
        int idx = lane + 32 * i;
        float4 a = b1[idx];
        float4 b = b2[idx];
        float4 bb = bias4[idx];
        float4 ww = w4[idx];
        s += fmaxf(a.x + b.x + bb.x, 0.f) * ww.x;
        s += fmaxf(a.y + b.y + bb.y, 0.f) * ww.y;
        s += fmaxf(a.z + b.z + bb.z, 0.f) * ww.z;
        s += fmaxf(a.w + b.w + bb.w, 0.f) * ww.w;
    }
    #pragma unroll
    for (int o = 16; o; o >>= 1) s += __shfl_down_sync(0xFFFFFFFFu, s, o);
    if (lane == 0) out[w] = s + m2b[0];
}

// ---------------- launch ----------------
extern "C" void kernel_launch(void* const* d_in, const int* in_sizes, int n_in,
                              void* d_out, int out_size) {
    const int*   ei   = (const int*)d_in[0];
    const float* uf   = (const float*)d_in[1];
    const float* pf   = (const float*)d_in[2];
    const float* uemb = (const float*)d_in[3];
    const float* pemb = (const float*)d_in[4];
    const float* uW   = (const float*)d_in[5];
    const float* ub   = (const float*)d_in[6];
    const float* pW   = (const float*)d_in[7];
    const float* pb   = (const float*)d_in[8];
    const float* c1W  = (const float*)d_in[9];
    const float* c1b  = (const float*)d_in[10];
    const float* c2W  = (const float*)d_in[11];
    const float* c2b  = (const float*)d_in[12];
    const float* m1W  = (const float*)d_in[13];
    const float* m1b  = (const float*)d_in[14];
    const float* m2W  = (const float*)d_in[15];
    const float* m2b  = (const float*)d_in[16];
    float* preds = (float*)d_out;

    float* xp;  float* hp;  int* degp; int* curp; int* totp;
    cudaGetSymbolAddress((void**)&xp, g_x);
    cudaGetSymbolAddress((void**)&hp, g_h);
    cudaGetSymbolAddress((void**)&degp, g_deg);
    cudaGetSymbolAddress((void**)&curp, g_cur);
    cudaGetSymbolAddress((void**)&totp, g_total);

    // ---- CSR build ----
    cudaMemsetAsync(degp, 0, NN * sizeof(int), 0);
    cudaMemsetAsync(curp, 0, NN * sizeof(int), 0);
    cudaMemsetAsync(totp, 0, sizeof(int), 0);
    k_degree<<<(NE + 255) / 256, 256>>>(ei);
    k_dinv<<<(NN + 255) / 256, 256>>>();
    k_offsets<<<(NN + 255) / 256, 256>>>();
    k_fill<<<(NE + 255) / 256, 256>>>(ei);

    dim3 gU((NU + 127) / 128, 2);
    dim3 gP((NP + 127) / 128, 2);
    dim3 gN((NN + 127) / 128, 2);

    // input transforms: x = feats @ W + b + emb
    gemm128<<<gU, 256>>>(uf, uW, ub, uemb, xp, NU, 128);
    gemm128<<<gP, 256>>>(pf, pW, pb, pemb, xp + (size_t)NU * D, NP, 128);

    const int nElem = (NN * 64 + 255) / 256;

    // conv1 (relu)
    gemm128<<<gN, 256>>>(xp, c1W, nullptr, nullptr, hp, NN, 256);
    k_gather<<<nElem, 256>>>(c1b, 1);

    // conv2 (no relu)
    gemm128<<<gN, 256>>>(xp, c2W, nullptr, nullptr, hp, NN, 256);
    k_gather<<<nElem, 256>>>(c2b, 0);

    // MLP factored through nodes
    gemm128<<<gU, 256>>>(xp, m1W, nullptr, nullptr, hp, NU, 256);
    gemm128<<<gP, 256>>>(xp + (size_t)NU * D, m1W + 256 * 256, nullptr, nullptr,
                         hp + (size_t)NU * D, NP, 256);

    // per-edge scoring
    k_edge_pred<<<(NE * 32 + 255) / 256, 256>>>(ei, m1b, m2W, m2b, preds);
}

// round 5
// speedup vs baseline: 2.5899x; 2.3785x over previous
#include <cuda_runtime.h>
#include <cstdint>

#define NU 100000
#define NP 50000
#define NN 150000   // NU + NP
#define NE 250000
#define D  256

// ---------------- scratch (static device globals; no allocation) ----------------
__device__ float g_x[(size_t)NN * D];   // node features / conv output
__device__ float g_h[(size_t)NN * D];   // x @ W  (also MLP node-partials)
__device__ float g_dinv[NN];
__device__ int   g_deg[NN];
__device__ int   g_off[NN];
__device__ int   g_cur[NN];
__device__ int   g_total;
__device__ int   g_adj[2 * NE];
__device__ float g_adn[2 * NE];
// transposed weights: uWt[256x128] pWt[256x128] c1Wt[256x256] c2Wt[256x256] m1Wt[256x512]
__device__ float g_wt[327680];
#define WT_U  0
#define WT_P  32768
#define WT_C1 65536
#define WT_C2 131072
#define WT_M1 196608

// ================= helpers =================
__device__ __forceinline__ uint32_t smem_u32(const void* p) {
    uint32_t a;
    asm("{ .reg .u64 t; cvta.to.shared.u64 t, %1; cvt.u32.u64 %0, t; }" : "=r"(a) : "l"(p));
    return a;
}
__device__ __forceinline__ uint32_t totf32(float x) {
    uint32_t u;
    asm("cvt.rna.tf32.f32 %0, %1;" : "=r"(u) : "f"(x));
    return u;
}
#define SWZ(off) ((off) ^ (((off) >> 3) & 0x70))
#define STS128(addr, a, b, c, d) \
    asm volatile("st.shared.v4.b32 [%0], {%1, %2, %3, %4};" \
                 :: "r"(addr), "r"(a), "r"(b), "r"(c), "r"(d) : "memory")
#define LDSM_X4(r0, r1, r2, r3, addr) \
    asm volatile("ldmatrix.sync.aligned.m8n8.x4.shared.b16 {%0, %1, %2, %3}, [%4];" \
                 : "=r"(r0), "=r"(r1), "=r"(r2), "=r"(r3) : "r"(addr))
#define MMA_TF32(c, a0, a1, a2, a3, b0, b1) \
    asm volatile("mma.sync.aligned.m16n8k8.row.col.f32.tf32.tf32.f32 " \
                 "{%0, %1, %2, %3}, {%4, %5, %6, %7}, {%8, %9}, {%0, %1, %2, %3};" \
                 : "+f"((c)[0]), "+f"((c)[1]), "+f"((c)[2]), "+f"((c)[3]) \
                 : "r"(a0), "r"(a1), "r"(a2), "r"(a3), "r"(b0), "r"(b1))

// ================= degree / CSR build =================
__global__ void k_degree(const int* __restrict__ ei) {
    int e = blockIdx.x * blockDim.x + threadIdx.x;
    if (e < NE) {
        atomicAdd(&g_deg[ei[e]], 1);
        atomicAdd(&g_deg[ei[NE + e]], 1);
    }
}
__global__ void k_dinv() {
    int n = blockIdx.x * blockDim.x + threadIdx.x;
    if (n < NN) g_dinv[n] = rsqrtf((float)g_deg[n] + 1.0f);
}
__global__ void k_offsets() {
    int n = blockIdx.x * blockDim.x + threadIdx.x;
    int lane = threadIdx.x & 31;
    int d = (n < NN) ? g_deg[n] : 0;
    int incl = d;
    #pragma unroll
    for (int o = 1; o < 32; o <<= 1) {
        int t = __shfl_up_sync(0xFFFFFFFFu, incl, o);
        if (lane >= o) incl += t;
    }
    int excl = incl - d;
    int base = 0;
    if (lane == 31) base = atomicAdd(&g_total, incl);
    base = __shfl_sync(0xFFFFFFFFu, base, 31);
    if (n < NN) g_off[n] = base + excl;
}
__global__ void k_fill(const int* __restrict__ ei) {
    int e = blockIdx.x * blockDim.x + threadIdx.x;
    if (e >= NE) return;
    int u = ei[e];
    int p = ei[NE + e];
    float du = g_dinv[u], dp = g_dinv[p];
    int idx = g_off[p] + atomicAdd(&g_cur[p], 1);
    g_adj[idx] = u;  g_adn[idx] = du;
    int idx2 = g_off[u] + atomicAdd(&g_cur[u], 1);
    g_adj[idx2] = p; g_adn[idx2] = dp;
}

// ================= weight transpose: Wt[n][k] = W[k][n] =================
__global__ void k_transpose(const float* __restrict__ W, float* __restrict__ Wt, int K, int N) {
    __shared__ float t[32][33];
    int bn = blockIdx.x * 32, bk = blockIdx.y * 32;
    #pragma unroll
    for (int i = 0; i < 4; i++) {
        int k = bk + threadIdx.y + i * 8, n = bn + threadIdx.x;
        if (k < K && n < N) t[threadIdx.y + i * 8][threadIdx.x] = W[(size_t)k * N + n];
    }
    __syncthreads();
    #pragma unroll
    for (int i = 0; i < 4; i++) {
        int n = bn + threadIdx.y + i * 8, k = bk + threadIdx.x;
        if (k < K && n < N) Wt[(size_t)n * K + k] = t[threadIdx.x][threadIdx.y + i * 8];
    }
}

// ================= tf32 mma.sync GEMM =================
// C[M,256] = A[M,K] @ Bt[colrange,K]^T (+bias)(+emb).  Bt row stride = ldb.
// Block tile 128x128x32, 8 warps (4 M x 2 N), warp tile 32x64 via m16n8k8.
// SMEM per stage: As[128][32] + Bs[128][32] tf32 (each row 128B, SW128 swizzle).
#define GEMM_SMEM (2 * 32768)

__global__ __launch_bounds__(256, 1) void gemm_tc(const float* __restrict__ A,
                                                  const float* __restrict__ Bt, int ldb,
                                                  const float* __restrict__ bias,
                                                  const float* __restrict__ emb,
                                                  float* __restrict__ C,
                                                  int M, int K) {
    extern __shared__ char smem[];
    uint32_t sb = smem_u32(smem);
    int tid = threadIdx.x;
    int lane = tid & 31;
    int wid = tid >> 5;
    int warpM = wid & 3;      // 4 groups of 32 rows
    int warpN = wid >> 2;     // 2 groups of 64 cols
    int rowBase = blockIdx.x * 128;
    int colBase = blockIdx.y * 128;

    float acc[2][8][4];
    #pragma unroll
    for (int mt = 0; mt < 2; mt++)
        #pragma unroll
        for (int j = 0; j < 8; j++)
            #pragma unroll
            for (int q = 0; q < 4; q++) acc[mt][j][q] = 0.f;

    float4 va[4], vb[4];

    #define LDG_CHUNK(k0)                                                          \
        {                                                                          \
            _Pragma("unroll")                                                      \
            for (int i = 0; i < 4; i++) {                                          \
                int lin = tid + i * 256;                                           \
                int r = lin >> 3, c4 = lin & 7;                                    \
                int gr = rowBase + r;                                              \
                va[i] = (gr < M)                                                   \
                    ? *(const float4*)&A[(size_t)gr * K + (k0) + c4 * 4]           \
                    : make_float4(0.f, 0.f, 0.f, 0.f);                             \
                vb[i] = *(const float4*)&Bt[(size_t)(colBase + r) * ldb + (k0) + c4 * 4]; \
            }                                                                      \
        }
    #define STS_CHUNK(st)                                                          \
        {                                                                          \
            uint32_t abase = sb + (st) * 32768;                                    \
            uint32_t bbase = abase + 16384;                                        \
            _Pragma("unroll")                                                      \
            for (int i = 0; i < 4; i++) {                                          \
                int lin = tid + i * 256;                                           \
                int r = lin >> 3, c4 = lin & 7;                                    \
                uint32_t off = SWZ((uint32_t)(r * 128 + c4 * 16));                 \
                STS128(abase + off, totf32(va[i].x), totf32(va[i].y),              \
                       totf32(va[i].z), totf32(va[i].w));                          \
                STS128(bbase + off, totf32(vb[i].x), totf32(vb[i].y),              \
                       totf32(vb[i].z), totf32(vb[i].w));                          \
            }                                                                      \
        }

    // per-thread ldmatrix row/col components (constant across chunks)
    int arow = warpM * 32 + (lane & 15);           // + mt*16
    int achunkoff = (lane >> 4);                   // 0 or 1 -> +2*ks
    int brow = warpN * 64 + ((lane >> 4) << 3) + (lane & 7);   // + jp*16
    int bchunkoff = ((lane >> 3) & 1);

    LDG_CHUNK(0);
    STS_CHUNK(0);
    __syncthreads();

    const int CH = K >> 5;
    for (int ch = 0; ch < CH; ch++) {
        int st = ch & 1;
        if (ch + 1 < CH) LDG_CHUNK((ch + 1) << 5);

        uint32_t abase = sb + st * 32768;
        uint32_t bbase = abase + 16384;
        #pragma unroll
        for (int ks = 0; ks < 4; ks++) {
            uint32_t af[2][4];
            #pragma unroll
            for (int mt = 0; mt < 2; mt++) {
                int r = arow + mt * 16;
                uint32_t addr = abase + SWZ((uint32_t)(r * 128 + (2 * ks + achunkoff) * 16));
                LDSM_X4(af[mt][0], af[mt][1], af[mt][2], af[mt][3], addr);
            }
            uint32_t bf[4][4];   // bf[jp] = {b0(2jp), b1(2jp), b0(2jp+1), b1(2jp+1)}
            #pragma unroll
            for (int jp = 0; jp < 4; jp++) {
                int r = brow + jp * 16;
                uint32_t addr = bbase + SWZ((uint32_t)(r * 128 + (2 * ks + bchunkoff) * 16));
                LDSM_X4(bf[jp][0], bf[jp][1], bf[jp][2], bf[jp][3], addr);
            }
            #pragma unroll
            for (int mt = 0; mt < 2; mt++)
                #pragma unroll
                for (int j = 0; j < 8; j++)
                    MMA_TF32(acc[mt][j], af[mt][0], af[mt][1], af[mt][2], af[mt][3],
                             bf[j >> 1][(j & 1) * 2], bf[j >> 1][(j & 1) * 2 + 1]);
        }
        if (ch + 1 < CH) {
            STS_CHUNK(st ^ 1);
            __syncthreads();
        }
    }

    // ---- epilogue: fragment rows -> gmem, fuse bias/emb ----
    #pragma unroll
    for (int mt = 0; mt < 2; mt++) {
        int r0 = rowBase + warpM * 32 + mt * 16 + (lane >> 2);
        int r1 = r0 + 8;
        #pragma unroll
        for (int j = 0; j < 8; j++) {
            int gc = colBase + warpN * 64 + j * 8 + (lane & 3) * 2;
            float2 v0 = make_float2(acc[mt][j][0], acc[mt][j][1]);
            float2 v1 = make_float2(acc[mt][j][2], acc[mt][j][3]);
            if (bias) {
                float2 bb = *(const float2*)&bias[gc];
                v0.x += bb.x; v0.y += bb.y;
                v1.x += bb.x; v1.y += bb.y;
            }
            if (r0 < M) {
                if (emb) {
                    float2 e0 = *(const float2*)&emb[(size_t)r0 * 256 + gc];
                    v0.x += e0.x; v0.y += e0.y;
                }
                *(float2*)&C[(size_t)r0 * 256 + gc] = v0;
            }
            if (r1 < M) {
                if (emb) {
                    float2 e1 = *(const float2*)&emb[(size_t)r1 * 256 + gc];
                    v1.x += e1.x; v1.y += e1.y;
                }
                *(float2*)&C[(size_t)r1 * 256 + gc] = v1;
            }
        }
    }
    #undef LDG_CHUNK
    #undef STS_CHUNK
}

// ================= fused GCN aggregation (CSR gather) =================
__global__ void k_gather(const float* __restrict__ b, int relu) {
    int i = blockIdx.x * blockDim.x + threadIdx.x;
    if (i >= NN * 64) return;
    int n = i >> 6;
    int c = (i & 63) << 2;
    float di = g_dinv[n];
    float s2 = di * di;
    float4 h = *(const float4*)&g_h[(size_t)n * D + c];
    float4 acc = make_float4(h.x * s2, h.y * s2, h.z * s2, h.w * s2);
    int s0 = g_off[n];
    int s1 = s0 + g_deg[n];
    for (int j = s0; j < s1; j++) {
        int a = g_adj[j];
        float nr = di * g_adn[j];
        float4 hv = *(const float4*)&g_h[(size_t)a * D + c];
        acc.x += hv.x * nr; acc.y += hv.y * nr;
        acc.z += hv.z * nr; acc.w += hv.w * nr;
    }
    float4 bb = *(const float4*)&b[c];
    acc.x += bb.x; acc.y += bb.y; acc.z += bb.z; acc.w += bb.w;
    if (relu) {
        acc.x = fmaxf(acc.x, 0.f); acc.y = fmaxf(acc.y, 0.f);
        acc.z = fmaxf(acc.z, 0.f); acc.w = fmaxf(acc.w, 0.f);
    }
    *(float4*)&g_x[(size_t)n * D + c] = acc;
}

// ================= per-edge MLP epilogue =================
__global__ void k_edge_pred(const int* __restrict__ ei,
                            const float* __restrict__ m1b,
                            const float* __restrict__ m2W,
                            const float* __restrict__ m2b,
                            float* __restrict__ out) {
    int gid = blockIdx.x * blockDim.x + threadIdx.x;
    int w = gid >> 5;
    int lane = gid & 31;
    if (w >= NE) return;
    int u = ei[w];
    int p = ei[NE + w];
    const float4* b1 = (const float4*)&g_h[(size_t)u * D];
    const float4* b2 = (const float4*)&g_h[(size_t)p * D];
    const float4* bias4 = (const float4*)m1b;
    const float4* w4 = (const float4*)m2W;
    float s = 0.f;
    #pragma unroll
    for (int i = 0; i < 2; i++) {
        int idx = lane + 32 * i;
        float4 a = b1[idx];
        float4 b = b2[idx];
        float4 bb = bias4[idx];
        float4 ww = w4[idx];
        s += fmaxf(a.x + b.x + bb.x, 0.f) * ww.x;
        s += fmaxf(a.y + b.y + bb.y, 0.f) * ww.y;
        s += fmaxf(a.z + b.z + bb.z, 0.f) * ww.z;
        s += fmaxf(a.w + b.w + bb.w, 0.f) * ww.w;
    }
    #pragma unroll
    for (int o = 16; o; o >>= 1) s += __shfl_down_sync(0xFFFFFFFFu, s, o);
    if (lane == 0) out[w] = s + m2b[0];
}

// ================= launch =================
extern "C" void kernel_launch(void* const* d_in, const int* in_sizes, int n_in,
                              void* d_out, int out_size) {
    const int*   ei   = (const int*)d_in[0];
    const float* uf   = (const float*)d_in[1];
    const float* pf   = (const float*)d_in[2];
    const float* uemb = (const float*)d_in[3];
    const float* pemb = (const float*)d_in[4];
    const float* uW   = (const float*)d_in[5];
    const float* ub   = (const float*)d_in[6];
    const float* pW   = (const float*)d_in[7];
    const float* pb   = (const float*)d_in[8];
    const float* c1W  = (const float*)d_in[9];
    const float* c1b  = (const float*)d_in[10];
    const float* c2W  = (const float*)d_in[11];
    const float* c2b  = (const float*)d_in[12];
    const float* m1W  = (const float*)d_in[13];
    const float* m1b  = (const float*)d_in[14];
    const float* m2W  = (const float*)d_in[15];
    const float* m2b  = (const float*)d_in[16];
    float* preds = (float*)d_out;

    float* xp;  float* hp;  float* wt;  int* degp; int* curp; int* totp;
    cudaGetSymbolAddress((void**)&xp, g_x);
    cudaGetSymbolAddress((void**)&hp, g_h);
    cudaGetSymbolAddress((void**)&wt, g_wt);
    cudaGetSymbolAddress((void**)&degp, g_deg);
    cudaGetSymbolAddress((void**)&curp, g_cur);
    cudaGetSymbolAddress((void**)&totp, g_total);

    cudaFuncSetAttribute(gemm_tc, cudaFuncAttributeMaxDynamicSharedMemorySize, GEMM_SMEM);

    // ---- CSR build ----
    cudaMemsetAsync(degp, 0, NN * sizeof(int), 0);
    cudaMemsetAsync(curp, 0, NN * sizeof(int), 0);
    cudaMemsetAsync(totp, 0, sizeof(int), 0);
    k_degree<<<(NE + 255) / 256, 256>>>(ei);
    k_dinv<<<(NN + 255) / 256, 256>>>();
    k_offsets<<<(NN + 255) / 256, 256>>>();
    k_fill<<<(NE + 255) / 256, 256>>>(ei);

    // ---- transpose weights into g_wt ----
    dim3 tb(32, 8);
    k_transpose<<<dim3(8, 4),  tb>>>(uW,  wt + WT_U,  128, 256);
    k_transpose<<<dim3(8, 4),  tb>>>(pW,  wt + WT_P,  128, 256);
    k_transpose<<<dim3(8, 8),  tb>>>(c1W, wt + WT_C1, 256, 256);
    k_transpose<<<dim3(8, 8),  tb>>>(c2W, wt + WT_C2, 256, 256);
    k_transpose<<<dim3(8, 16), tb>>>(m1W, wt + WT_M1, 512, 256);

    dim3 gU((NU + 127) / 128, 2);
    dim3 gP((NP + 127) / 128, 2);
    dim3 gN((NN + 127) / 128, 2);
    const int nElem = (NN * 64 + 255) / 256;

    // input transforms: x = feats @ W + b + emb
    gemm_tc<<<gU, 256, GEMM_SMEM>>>(uf, wt + WT_U, 128, ub, uemb, xp, NU, 128);
    gemm_tc<<<gP, 256, GEMM_SMEM>>>(pf, wt + WT_P, 128, pb, pemb, xp + (size_t)NU * D, NP, 128);

    // conv1 (relu)
    gemm_tc<<<gN, 256, GEMM_SMEM>>>(xp, wt + WT_C1, 256, nullptr, nullptr, hp, NN, 256);
    k_gather<<<nElem, 256>>>(c1b, 1);

    // conv2 (no relu)
    gemm_tc<<<gN, 256, GEMM_SMEM>>>(xp, wt + WT_C2, 256, nullptr, nullptr, hp, NN, 256);
    k_gather<<<nElem, 256>>>(c2b, 0);

    // MLP factored through nodes: top half of m1W for users, bottom for products
    gemm_tc<<<gU, 256, GEMM_SMEM>>>(xp, wt + WT_M1, 512, nullptr, nullptr, hp, NU, 256);
    gemm_tc<<<gP, 256, GEMM_SMEM>>>(xp + (size_t)NU * D, wt + WT_M1 + 256, 512,
                                    nullptr, nullptr, hp + (size_t)NU * D, NP, 256);

    // per-edge scoring
    k_edge_pred<<<(NE * 32 + 255) / 256, 256>>>(ei, m1b, m2W, m2b, preds);
}

// round 6
// speedup vs baseline: 2.9521x; 1.1399x over previous
#include <cuda_runtime.h>
#include <cstdint>

#define NU 100000
#define NP 50000
#define NN 150000   // NU + NP
#define NE 250000
#define D  256

// ---------------- scratch (static device globals; no allocation) ----------------
__device__ float g_x[(size_t)NN * D];   // node features / conv output
__device__ float g_h[(size_t)NN * D];   // x @ W  (also MLP node-partials)
__device__ float g_dinv[NN];
__device__ int   g_deg[NN];
__device__ int   g_off[NN];
__device__ int   g_cur[NN];
__device__ int   g_total;
__device__ int   g_adj[2 * NE];
__device__ float g_adn[2 * NE];
// transposed weights: uWt[256x128] pWt[256x128] c1Wt[256x256] c2Wt[256x256] m1Wt[256x512]
__device__ float g_wt[327680];
#define WT_U  0
#define WT_P  32768
#define WT_C1 65536
#define WT_C2 131072
#define WT_M1 196608

// ================= helpers =================
__device__ __forceinline__ uint32_t smem_u32(const void* p) {
    uint32_t a;
    asm("{ .reg .u64 t; cvta.to.shared.u64 t, %1; cvt.u32.u64 %0, t; }" : "=r"(a) : "l"(p));
    return a;
}
__device__ __forceinline__ uint32_t totf32(float x) {
    uint32_t u;
    asm("cvt.rna.tf32.f32 %0, %1;" : "=r"(u) : "f"(x));
    return u;
}
__device__ __forceinline__ uint32_t tf32r(uint32_t x) {   // round fp32 bits -> tf32 bits
    return totf32(__uint_as_float(x));
}
#define SWZ(off) ((off) ^ (((off) >> 3) & 0x70))
#define LDSM_X4(r0, r1, r2, r3, addr) \
    asm volatile("ldmatrix.sync.aligned.m8n8.x4.shared.b16 {%0, %1, %2, %3}, [%4];" \
                 : "=r"(r0), "=r"(r1), "=r"(r2), "=r"(r3) : "r"(addr))
#define MMA_TF32(c, a0, a1, a2, a3, b0, b1) \
    asm volatile("mma.sync.aligned.m16n8k8.row.col.f32.tf32.tf32.f32 " \
                 "{%0, %1, %2, %3}, {%4, %5, %6, %7}, {%8, %9}, {%0, %1, %2, %3};" \
                 : "+f"((c)[0]), "+f"((c)[1]), "+f"((c)[2]), "+f"((c)[3]) \
                 : "r"(a0), "r"(a1), "r"(a2), "r"(a3), "r"(b0), "r"(b1))
#define CP_ASYNC16(dst, src, sz) \
    asm volatile("cp.async.cg.shared.global [%0], [%1], 16, %2;" \
                 :: "r"(dst), "l"(src), "r"(sz) : "memory")
#define CP_COMMIT() asm volatile("cp.async.commit_group;" ::: "memory")
#define CP_WAIT2()  asm volatile("cp.async.wait_group 2;" ::: "memory")

// ================= degree / CSR build =================
__global__ void k_degree(const int* __restrict__ ei) {
    int e = blockIdx.x * blockDim.x + threadIdx.x;
    if (e < NE) {
        atomicAdd(&g_deg[ei[e]], 1);
        atomicAdd(&g_deg[ei[NE + e]], 1);
    }
}
__global__ void k_dinv() {
    int n = blockIdx.x * blockDim.x + threadIdx.x;
    if (n < NN) g_dinv[n] = rsqrtf((float)g_deg[n] + 1.0f);
}
__global__ void k_offsets() {
    int n = blockIdx.x * blockDim.x + threadIdx.x;
    int lane = threadIdx.x & 31;
    int d = (n < NN) ? g_deg[n] : 0;
    int incl = d;
    #pragma unroll
    for (int o = 1; o < 32; o <<= 1) {
        int t = __shfl_up_sync(0xFFFFFFFFu, incl, o);
        if (lane >= o) incl += t;
    }
    int excl = incl - d;
    int base = 0;
    if (lane == 31) base = atomicAdd(&g_total, incl);
    base = __shfl_sync(0xFFFFFFFFu, base, 31);
    if (n < NN) g_off[n] = base + excl;
}
__global__ void k_fill(const int* __restrict__ ei) {
    int e = blockIdx.x * blockDim.x + threadIdx.x;
    if (e >= NE) return;
    int u = ei[e];
    int p = ei[NE + e];
    float du = g_dinv[u], dp = g_dinv[p];
    int idx = g_off[p] + atomicAdd(&g_cur[p], 1);
    g_adj[idx] = u;  g_adn[idx] = du;
    int idx2 = g_off[u] + atomicAdd(&g_cur[u], 1);
    g_adj[idx2] = p; g_adn[idx2] = dp;
}

// ================= weight transpose: Wt[n][k] = W[k][n] =================
__global__ void k_transpose(const float* __restrict__ W, float* __restrict__ Wt, int K, int N) {
    __shared__ float t[32][33];
    int bn = blockIdx.x * 32, bk = blockIdx.y * 32;
    #pragma unroll
    for (int i = 0; i < 4; i++) {
        int k = bk + threadIdx.y + i * 8, n = bn + threadIdx.x;
        if (k < K && n < N) t[threadIdx.y + i * 8][threadIdx.x] = W[(size_t)k * N + n];
    }
    __syncthreads();
    #pragma unroll
    for (int i = 0; i < 4; i++) {
        int n = bn + threadIdx.y + i * 8, k = bk + threadIdx.x;
        if (k < K && n < N) Wt[(size_t)n * K + k] = t[threadIdx.x][threadIdx.y + i * 8];
    }
}

// ================= tf32 mma.sync GEMM, cp.async 3-stage pipeline =================
// C[M,256] = A[M,K] @ Bt[colrange,K]^T (+bias)(+emb).  Bt row stride = ldb.
// Block tile 128x128x32, 8 warps (4 M x 2 N), warp tile 32x64 via m16n8k8.
// SMEM: 3 stages x (As[128][32] + Bs[128][32]) raw fp32, rows 128B, SW128 swizzle.
// tf32 rounding (cvt.rna) applied AFTER ldmatrix on fragment registers.
#define NSTAGE 3
#define STAGE_BYTES 32768
#define GEMM_SMEM (NSTAGE * STAGE_BYTES)

__global__ __launch_bounds__(256) void gemm_tc(const float* __restrict__ A,
                                               const float* __restrict__ Bt, int ldb,
                                               const float* __restrict__ bias,
                                               const float* __restrict__ emb,
                                               float* __restrict__ C,
                                               int M, int K) {
    extern __shared__ char smem[];
    uint32_t sb = smem_u32(smem);
    int tid = threadIdx.x;
    int lane = tid & 31;
    int wid = tid >> 5;
    int warpM = wid & 3;      // 4 groups of 32 rows
    int warpN = wid >> 2;     // 2 groups of 64 cols
    int rowBase = blockIdx.x * 128;
    int colBase = blockIdx.y * 128;

    float acc[2][8][4];
    #pragma unroll
    for (int mt = 0; mt < 2; mt++)
        #pragma unroll
        for (int j = 0; j < 8; j++)
            #pragma unroll
            for (int q = 0; q < 4; q++) acc[mt][j][q] = 0.f;

    // per-thread fill coordinates (4 float4 per thread for A, 4 for B)
    const int fr  = tid >> 3;          // rows handled: fr, fr+32, fr+64, fr+96
    const int fc4 = tid & 7;           // float4 column within 32-float chunk
    const float* aSrcBase = A  + (size_t)(rowBase + fr) * K + fc4 * 4;
    const float* bSrcBase = Bt + (size_t)(colBase + fr) * ldb + fc4 * 4;

    #define ISSUE_CHUNK(c)                                                         \
        {                                                                          \
            int k0 = (c) << 5;                                                     \
            uint32_t abase = sb + ((c) % NSTAGE) * STAGE_BYTES;                    \
            uint32_t bbase = abase + 16384;                                        \
            _Pragma("unroll")                                                      \
            for (int i = 0; i < 4; i++) {                                          \
                int r = fr + i * 32;                                               \
                uint32_t off = SWZ((uint32_t)(r * 128 + fc4 * 16));                \
                uint32_t asz = (rowBase + r < M) ? 16u : 0u;                       \
                CP_ASYNC16(abase + off, aSrcBase + (size_t)(i * 32) * K + k0, asz);\
                CP_ASYNC16(bbase + off, bSrcBase + (size_t)(i * 32) * ldb + k0, 16u);\
            }                                                                      \
        }

    // per-thread ldmatrix row/col components (constant across chunks)
    const int arow = warpM * 32 + (lane & 15);                        // + mt*16
    const int achunkoff = (lane >> 4);                                // 0/1
    const int brow = warpN * 64 + ((lane >> 4) << 3) + (lane & 7);    // + jp*16
    const int bchunkoff = ((lane >> 3) & 1);

    const int CH = K >> 5;
    // prologue: issue NSTAGE-1 chunks
    ISSUE_CHUNK(0); CP_COMMIT();
    if (CH > 1) { ISSUE_CHUNK(1); }
    CP_COMMIT();

    for (int ch = 0; ch < CH; ch++) {
        if (ch + NSTAGE - 1 < CH) { ISSUE_CHUNK(ch + NSTAGE - 1); }
        CP_COMMIT();
        CP_WAIT2();
        __syncthreads();

        uint32_t abase = sb + (ch % NSTAGE) * STAGE_BYTES;
        uint32_t bbase = abase + 16384;
        #pragma unroll
        for (int ks = 0; ks < 4; ks++) {
            uint32_t af[2][4];
            #pragma unroll
            for (int mt = 0; mt < 2; mt++) {
                int r = arow + mt * 16;
                uint32_t addr = abase + SWZ((uint32_t)(r * 128 + (2 * ks + achunkoff) * 16));
                LDSM_X4(af[mt][0], af[mt][1], af[mt][2], af[mt][3], addr);
                #pragma unroll
                for (int q = 0; q < 4; q++) af[mt][q] = tf32r(af[mt][q]);
            }
            uint32_t bf[4][4];   // bf[jp] = {b0(2jp), b1(2jp), b0(2jp+1), b1(2jp+1)}
            #pragma unroll
            for (int jp = 0; jp < 4; jp++) {
                int r = brow + jp * 16;
                uint32_t addr = bbase + SWZ((uint32_t)(r * 128 + (2 * ks + bchunkoff) * 16));
                LDSM_X4(bf[jp][0], bf[jp][1], bf[jp][2], bf[jp][3], addr);
                #pragma unroll
                for (int q = 0; q < 4; q++) bf[jp][q] = tf32r(bf[jp][q]);
            }
            #pragma unroll
            for (int mt = 0; mt < 2; mt++)
                #pragma unroll
                for (int j = 0; j < 8; j++)
                    MMA_TF32(acc[mt][j], af[mt][0], af[mt][1], af[mt][2], af[mt][3],
                             bf[j >> 1][(j & 1) * 2], bf[j >> 1][(j & 1) * 2 + 1]);
        }
        __syncthreads();
    }

    // ---- epilogue: fragment rows -> gmem, fuse bias/emb ----
    #pragma unroll
    for (int mt = 0; mt < 2; mt++) {
        int r0 = rowBase + warpM * 32 + mt * 16 + (lane >> 2);
        int r1 = r0 + 8;
        #pragma unroll
        for (int j = 0; j < 8; j++) {
            int gc = colBase + warpN * 64 + j * 8 + (lane & 3) * 2;
            float2 v0 = make_float2(acc[mt][j][0], acc[mt][j][1]);
            float2 v1 = make_float2(acc[mt][j][2], acc[mt][j][3]);
            if (bias) {
                float2 bb = *(const float2*)&bias[gc];
                v0.x += bb.x; v0.y += bb.y;
                v1.x += bb.x; v1.y += bb.y;
            }
            if (r0 < M) {
                if (emb) {
                    float2 e0 = *(const float2*)&emb[(size_t)r0 * 256 + gc];
                    v0.x += e0.x; v0.y += e0.y;
                }
                *(float2*)&C[(size_t)r0 * 256 + gc] = v0;
            }
            if (r1 < M) {
                if (emb) {
                    float2 e1 = *(const float2*)&emb[(size_t)r1 * 256 + gc];
                    v1.x += e1.x; v1.y += e1.y;
                }
                *(float2*)&C[(size_t)r1 * 256 + gc] = v1;
            }
        }
    }
    #undef ISSUE_CHUNK
}

// ================= fused GCN aggregation (CSR gather) =================
__global__ void k_gather(const float* __restrict__ b, int relu) {
    int i = blockIdx.x * blockDim.x + threadIdx.x;
    if (i >= NN * 64) return;
    int n = i >> 6;
    int c = (i & 63) << 2;
    float di = g_dinv[n];
    float s2 = di * di;
    float4 h = *(const float4*)&g_h[(size_t)n * D + c];
    float4 acc = make_float4(h.x * s2, h.y * s2, h.z * s2, h.w * s2);
    int s0 = g_off[n];
    int s1 = s0 + g_deg[n];
    for (int j = s0; j < s1; j++) {
        int a = g_adj[j];
        float nr = di * g_adn[j];
        float4 hv = *(const float4*)&g_h[(size_t)a * D + c];
        acc.x += hv.x * nr; acc.y += hv.y * nr;
        acc.z += hv.z * nr; acc.w += hv.w * nr;
    }
    float4 bb = *(const float4*)&b[c];
    acc.x += bb.x; acc.y += bb.y; acc.z += bb.z; acc.w += bb.w;
    if (relu) {
        acc.x = fmaxf(acc.x, 0.f); acc.y = fmaxf(acc.y, 0.f);
        acc.z = fmaxf(acc.z, 0.f); acc.w = fmaxf(acc.w, 0.f);
    }
    *(float4*)&g_x[(size_t)n * D + c] = acc;
}

// ================= per-edge MLP epilogue =================
__global__ void k_edge_pred(const int* __restrict__ ei,
                            const float* __restrict__ m1b,
                            const float* __restrict__ m2W,
                            const float* __restrict__ m2b,
                            float* __restrict__ out) {
    int gid = blockIdx.x * blockDim.x + threadIdx.x;
    int w = gid >> 5;
    int lane = gid & 31;
    if (w >= NE) return;
    int u = ei[w];
    int p = ei[NE + w];
    const float4* b1 = (const float4*)&g_h[(size_t)u * D];
    const float4* b2 = (const float4*)&g_h[(size_t)p * D];
    const float4* bias4 = (const float4*)m1b;
    const float4* w4 = (const float4*)m2W;
    float s = 0.f;
    #pragma unroll
    for (int i = 0; i < 2; i++) {
        int idx = lane + 32 * i;
        float4 a = b1[idx];
        float4 b = b2[idx];
        float4 bb = bias4[idx];
        float4 ww = w4[idx];
        s += fmaxf(a.x + b.x + bb.x, 0.f) * ww.x;
        s += fmaxf(a.y + b.y + bb.y, 0.f) * ww.y;
        s += fmaxf(a.z + b.z + bb.z, 0.f) * ww.z;
        s += fmaxf(a.w + b.w + bb.w, 0.f) * ww.w;
    }
    #pragma unroll
    for (int o = 16; o; o >>= 1) s += __shfl_down_sync(0xFFFFFFFFu, s, o);
    if (lane == 0) out[w] = s + m2b[0];
}

// ================= launch =================
extern "C" void kernel_launch(void* const* d_in, const int* in_sizes, int n_in,
                              void* d_out, int out_size) {
    const int*   ei   = (const int*)d_in[0];
    const float* uf   = (const float*)d_in[1];
    const float* pf   = (const float*)d_in[2];
    const float* uemb = (const float*)d_in[3];
    const float* pemb = (const float*)d_in[4];
    const float* uW   = (const float*)d_in[5];
    const float* ub   = (const float*)d_in[6];
    const float* pW   = (const float*)d_in[7];
    const float* pb   = (const float*)d_in[8];
    const float* c1W  = (const float*)d_in[9];
    const float* c1b  = (const float*)d_in[10];
    const float* c2W  = (const float*)d_in[11];
    const float* c2b  = (const float*)d_in[12];
    const float* m1W  = (const float*)d_in[13];
    const float* m1b  = (const float*)d_in[14];
    const float* m2W  = (const float*)d_in[15];
    const float* m2b  = (const float*)d_in[16];
    float* preds = (float*)d_out;

    float* xp;  float* hp;  float* wt;  int* degp; int* curp; int* totp;
    cudaGetSymbolAddress((void**)&xp, g_x);
    cudaGetSymbolAddress((void**)&hp, g_h);
    cudaGetSymbolAddress((void**)&wt, g_wt);
    cudaGetSymbolAddress((void**)&degp, g_deg);
    cudaGetSymbolAddress((void**)&curp, g_cur);
    cudaGetSymbolAddress((void**)&totp, g_total);

    cudaFuncSetAttribute(gemm_tc, cudaFuncAttributeMaxDynamicSharedMemorySize, GEMM_SMEM);

    // ---- CSR build ----
    cudaMemsetAsync(degp, 0, NN * sizeof(int), 0);
    cudaMemsetAsync(curp, 0, NN * sizeof(int), 0);
    cudaMemsetAsync(totp, 0, sizeof(int), 0);
    k_degree<<<(NE + 255) / 256, 256>>>(ei);
    k_dinv<<<(NN + 255) / 256, 256>>>();
    k_offsets<<<(NN + 255) / 256, 256>>>();
    k_fill<<<(NE + 255) / 256, 256>>>(ei);

    // ---- transpose weights into g_wt ----
    dim3 tb(32, 8);
    k_transpose<<<dim3(8, 4),  tb>>>(uW,  wt + WT_U,  128, 256);
    k_transpose<<<dim3(8, 4),  tb>>>(pW,  wt + WT_P,  128, 256);
    k_transpose<<<dim3(8, 8),  tb>>>(c1W, wt + WT_C1, 256, 256);
    k_transpose<<<dim3(8, 8),  tb>>>(c2W, wt + WT_C2, 256, 256);
    k_transpose<<<dim3(8, 16), tb>>>(m1W, wt + WT_M1, 512, 256);

    dim3 gU((NU + 127) / 128, 2);
    dim3 gP((NP + 127) / 128, 2);
    dim3 gN((NN + 127) / 128, 2);
    const int nElem = (NN * 64 + 255) / 256;

    // input transforms: x = feats @ W + b + emb
    gemm_tc<<<gU, 256, GEMM_SMEM>>>(uf, wt + WT_U, 128, ub, uemb, xp, NU, 128);
    gemm_tc<<<gP, 256, GEMM_SMEM>>>(pf, wt + WT_P, 128, pb, pemb, xp + (size_t)NU * D, NP, 128);

    // conv1 (relu)
    gemm_tc<<<gN, 256, GEMM_SMEM>>>(xp, wt + WT_C1, 256, nullptr, nullptr, hp, NN, 256);
    k_gather<<<nElem, 256>>>(c1b, 1);

    // conv2 (no relu)
    gemm_tc<<<gN, 256, GEMM_SMEM>>>(xp, wt + WT_C2, 256, nullptr, nullptr, hp, NN, 256);
    k_gather<<<nElem, 256>>>(c2b, 0);

    // MLP factored through nodes: top half of m1W for users, bottom for products
    gemm_tc<<<gU, 256, GEMM_SMEM>>>(xp, wt + WT_M1, 512, nullptr, nullptr, hp, NU, 256);
    gemm_tc<<<gP, 256, GEMM_SMEM>>>(xp + (size_t)NU * D, wt + WT_M1 + 256, 512,
                                    nullptr, nullptr, hp + (size_t)NU * D, NP, 256);

    // per-edge scoring
    k_edge_pred<<<(NE * 32 + 255) / 256, 256>>>(ei, m1b, m2W, m2b, preds);
}

// round 7
// speedup vs baseline: 3.1939x; 1.0819x over previous
#include <cuda_runtime.h>
#include <cstdint>

#define NU 100000
#define NP 50000
#define NN 150000   // NU + NP
#define NE 250000
#define D  256

// ---------------- scratch (static device globals; no allocation) ----------------
__device__ float g_x[(size_t)NN * D];   // node features / conv output
__device__ float g_h[(size_t)NN * D];   // x @ W  (also MLP node-partials)
__device__ float g_dinv[NN];
__device__ int   g_deg[NN];
__device__ int   g_off[NN];
__device__ int   g_cur[NN];
__device__ int   g_total;
__device__ int   g_adj[2 * NE];
__device__ float g_adn[2 * NE];
// transposed (and tf32-pre-rounded) weights:
// uWt[256x128] pWt[256x128] c1Wt[256x256] c2Wt[256x256] m1Wt[256x512]
__device__ float g_wt[327680];
#define WT_U  0
#define WT_P  32768
#define WT_C1 65536
#define WT_C2 131072
#define WT_M1 196608

// ================= helpers =================
__device__ __forceinline__ uint32_t smem_u32(const void* p) {
    uint32_t a;
    asm("{ .reg .u64 t; cvta.to.shared.u64 t, %1; cvt.u32.u64 %0, t; }" : "=r"(a) : "l"(p));
    return a;
}
__device__ __forceinline__ uint32_t totf32(float x) {
    uint32_t u;
    asm("cvt.rna.tf32.f32 %0, %1;" : "=r"(u) : "f"(x));
    return u;
}
__device__ __forceinline__ uint32_t tf32r(uint32_t x) {   // round fp32 bits -> tf32 bits
    return totf32(__uint_as_float(x));
}
#define SWZ(off) ((off) ^ (((off) >> 3) & 0x70))
#define LDSM_X4(r0, r1, r2, r3, addr) \
    asm volatile("ldmatrix.sync.aligned.m8n8.x4.shared.b16 {%0, %1, %2, %3}, [%4];" \
                 : "=r"(r0), "=r"(r1), "=r"(r2), "=r"(r3) : "r"(addr))
#define MMA_TF32(c, a0, a1, a2, a3, b0, b1) \
    asm volatile("mma.sync.aligned.m16n8k8.row.col.f32.tf32.tf32.f32 " \
                 "{%0, %1, %2, %3}, {%4, %5, %6, %7}, {%8, %9}, {%0, %1, %2, %3};" \
                 : "+f"((c)[0]), "+f"((c)[1]), "+f"((c)[2]), "+f"((c)[3]) \
                 : "r"(a0), "r"(a1), "r"(a2), "r"(a3), "r"(b0), "r"(b1))
#define CP_ASYNC16(dst, src, sz) \
    asm volatile("cp.async.cg.shared.global [%0], [%1], 16, %2;" \
                 :: "r"(dst), "l"(src), "r"(sz) : "memory")
#define CP_COMMIT() asm volatile("cp.async.commit_group;" ::: "memory")
#define CP_WAIT2()  asm volatile("cp.async.wait_group 2;" ::: "memory")

// ================= degree / CSR build =================
__global__ void k_degree(const int* __restrict__ ei) {
    int e = blockIdx.x * blockDim.x + threadIdx.x;
    if (e < NE) {
        atomicAdd(&g_deg[ei[e]], 1);
        atomicAdd(&g_deg[ei[NE + e]], 1);
    }
}
// offsets + dinv + cur-zero fused
__global__ void k_offsets() {
    int n = blockIdx.x * blockDim.x + threadIdx.x;
    int lane = threadIdx.x & 31;
    int d = (n < NN) ? g_deg[n] : 0;
    int incl = d;
    #pragma unroll
    for (int o = 1; o < 32; o <<= 1) {
        int t = __shfl_up_sync(0xFFFFFFFFu, incl, o);
        if (lane >= o) incl += t;
    }
    int excl = incl - d;
    int base = 0;
    if (lane == 31) base = atomicAdd(&g_total, incl);
    base = __shfl_sync(0xFFFFFFFFu, base, 31);
    if (n < NN) {
        g_off[n] = base + excl;
        g_cur[n] = 0;
        g_dinv[n] = rsqrtf((float)d + 1.0f);
    }
}
__global__ void k_fill(const int* __restrict__ ei) {
    int e = blockIdx.x * blockDim.x + threadIdx.x;
    if (e >= NE) return;
    int u = ei[e];
    int p = ei[NE + e];
    float du = g_dinv[u], dp = g_dinv[p];
    int idx = g_off[p] + atomicAdd(&g_cur[p], 1);
    g_adj[idx] = u;  g_adn[idx] = du;
    int idx2 = g_off[u] + atomicAdd(&g_cur[u], 1);
    g_adj[idx2] = p; g_adn[idx2] = dp;
}

// ========= weight transpose + tf32 pre-round: Wt[n][k] = tf32(W[k][n]) =========
__global__ void k_transpose(const float* __restrict__ W, float* __restrict__ Wt, int K, int N) {
    __shared__ float t[32][33];
    int bn = blockIdx.x * 32, bk = blockIdx.y * 32;
    #pragma unroll
    for (int i = 0; i < 4; i++) {
        int k = bk + threadIdx.y + i * 8, n = bn + threadIdx.x;
        if (k < K && n < N) t[threadIdx.y + i * 8][threadIdx.x] = W[(size_t)k * N + n];
    }
    __syncthreads();
    #pragma unroll
    for (int i = 0; i < 4; i++) {
        int n = bn + threadIdx.y + i * 8, k = bk + threadIdx.x;
        if (k < K && n < N)
            Wt[(size_t)n * K + k] =
                __uint_as_float(totf32(t[threadIdx.x][threadIdx.y + i * 8]));
    }
}

// ================= tf32 mma.sync GEMM, cp.async 3-stage pipeline =================
// C[M,256] = A[M,K] @ Bt[colrange,K]^T (+bias)(+emb).  Bt row stride = ldb.
// Block tile 128x128x32, 8 warps (4 M x 2 N), warp tile 32x64 via m16n8k8.
// SMEM: 3 stages x (As[128][32] + Bs[128][32]), rows 128B, SW128 swizzle.
// A fragments tf32-rounded after ldmatrix; B (weights) pre-rounded at transpose.
#define NSTAGE 3
#define STAGE_BYTES 32768
#define GEMM_SMEM (NSTAGE * STAGE_BYTES)

__global__ __launch_bounds__(256, 2) void gemm_tc(const float* __restrict__ A,
                                                  const float* __restrict__ Bt, int ldb,
                                                  const float* __restrict__ bias,
                                                  const float* __restrict__ emb,
                                                  float* __restrict__ C,
                                                  int M, int K) {
    extern __shared__ char smem[];
    uint32_t sb = smem_u32(smem);
    int tid = threadIdx.x;
    int lane = tid & 31;
    int wid = tid >> 5;
    int warpM = wid & 3;      // 4 groups of 32 rows
    int warpN = wid >> 2;     // 2 groups of 64 cols
    int rowBase = blockIdx.x * 128;
    int colBase = blockIdx.y * 128;

    float acc[2][8][4];
    #pragma unroll
    for (int mt = 0; mt < 2; mt++)
        #pragma unroll
        for (int j = 0; j < 8; j++)
            #pragma unroll
            for (int q = 0; q < 4; q++) acc[mt][j][q] = 0.f;

    // per-thread fill coordinates (4 float4 per thread for A, 4 for B)
    const int fr  = tid >> 3;          // rows handled: fr, fr+32, fr+64, fr+96
    const int fc4 = tid & 7;           // float4 column within 32-float chunk
    const float* aSrcBase = A  + (size_t)(rowBase + fr) * K + fc4 * 4;
    const float* bSrcBase = Bt + (size_t)(colBase + fr) * ldb + fc4 * 4;

    #define ISSUE_CHUNK(c)                                                         \
        {                                                                          \
            int k0 = (c) << 5;                                                     \
            uint32_t abase = sb + ((c) % NSTAGE) * STAGE_BYTES;                    \
            uint32_t bbase = abase + 16384;                                        \
            _Pragma("unroll")                                                      \
            for (int i = 0; i < 4; i++) {                                          \
                int r = fr + i * 32;                                               \
                uint32_t off = SWZ((uint32_t)(r * 128 + fc4 * 16));                \
                uint32_t asz = (rowBase + r < M) ? 16u : 0u;                       \
                CP_ASYNC16(abase + off, aSrcBase + (size_t)(i * 32) * K + k0, asz);\
                CP_ASYNC16(bbase + off, bSrcBase + (size_t)(i * 32) * ldb + k0, 16u);\
            }                                                                      \
        }

    // per-thread ldmatrix row/col components (constant across chunks)
    const int arow = warpM * 32 + (lane & 15);                        // + mt*16
    const int achunkoff = (lane >> 4);                                // 0/1
    const int brow = warpN * 64 + ((lane >> 4) << 3) + (lane & 7);    // + jp*16
    const int bchunkoff = ((lane >> 3) & 1);

    const int CH = K >> 5;
    // prologue: issue NSTAGE-1 chunks
    ISSUE_CHUNK(0); CP_COMMIT();
    if (CH > 1) { ISSUE_CHUNK(1); }
    CP_COMMIT();

    for (int ch = 0; ch < CH; ch++) {
        if (ch + NSTAGE - 1 < CH) { ISSUE_CHUNK(ch + NSTAGE - 1); }
        CP_COMMIT();
        CP_WAIT2();
        __syncthreads();

        uint32_t abase = sb + (ch % NSTAGE) * STAGE_BYTES;
        uint32_t bbase = abase + 16384;
        #pragma unroll
        for (int ks = 0; ks < 4; ks++) {
            uint32_t af[2][4];
            #pragma unroll
            for (int mt = 0; mt < 2; mt++) {
                int r = arow + mt * 16;
                uint32_t addr = abase + SWZ((uint32_t)(r * 128 + (2 * ks + achunkoff) * 16));
                LDSM_X4(af[mt][0], af[mt][1], af[mt][2], af[mt][3], addr);
                #pragma unroll
                for (int q = 0; q < 4; q++) af[mt][q] = tf32r(af[mt][q]);
            }
            uint32_t bf[4][4];   // bf[jp] = {b0(2jp), b1(2jp), b0(2jp+1), b1(2jp+1)}
            #pragma unroll
            for (int jp = 0; jp < 4; jp++) {
                int r = brow + jp * 16;
                uint32_t addr = bbase + SWZ((uint32_t)(r * 128 + (2 * ks + bchunkoff) * 16));
                LDSM_X4(bf[jp][0], bf[jp][1], bf[jp][2], bf[jp][3], addr);
            }
            #pragma unroll
            for (int mt = 0; mt < 2; mt++)
                #pragma unroll
                for (int j = 0; j < 8; j++)
                    MMA_TF32(acc[mt][j], af[mt][0], af[mt][1], af[mt][2], af[mt][3],
                             bf[j >> 1][(j & 1) * 2], bf[j >> 1][(j & 1) * 2 + 1]);
        }
        __syncthreads();
    }

    // ---- epilogue: fragment rows -> gmem, fuse bias/emb ----
    #pragma unroll
    for (int mt = 0; mt < 2; mt++) {
        int r0 = rowBase + warpM * 32 + mt * 16 + (lane >> 2);
        int r1 = r0 + 8;
        #pragma unroll
        for (int j = 0; j < 8; j++) {
            int gc = colBase + warpN * 64 + j * 8 + (lane & 3) * 2;
            float2 v0 = make_float2(acc[mt][j][0], acc[mt][j][1]);
            float2 v1 = make_float2(acc[mt][j][2], acc[mt][j][3]);
            if (bias) {
                float2 bb = *(const float2*)&bias[gc];
                v0.x += bb.x; v0.y += bb.y;
                v1.x += bb.x; v1.y += bb.y;
            }
            if (r0 < M) {
                if (emb) {
                    float2 e0 = *(const float2*)&emb[(size_t)r0 * 256 + gc];
                    v0.x += e0.x; v0.y += e0.y;
                }
                *(float2*)&C[(size_t)r0 * 256 + gc] = v0;
            }
            if (r1 < M) {
                if (emb) {
                    float2 e1 = *(const float2*)&emb[(size_t)r1 * 256 + gc];
                    v1.x += e1.x; v1.y += e1.y;
                }
                *(float2*)&C[(size_t)r1 * 256 + gc] = v1;
            }
        }
    }
    #undef ISSUE_CHUNK
}

// ================= fused GCN aggregation (CSR gather) =================
__global__ void k_gather(const float* __restrict__ b, int relu) {
    int i = blockIdx.x * blockDim.x + threadIdx.x;
    if (i >= NN * 64) return;
    int n = i >> 6;
    int c = (i & 63) << 2;
    float di = g_dinv[n];
    float s2 = di * di;
    float4 h = *(const float4*)&g_h[(size_t)n * D + c];
    float4 acc = make_float4(h.x * s2, h.y * s2, h.z * s2, h.w * s2);
    int s0 = g_off[n];
    int s1 = s0 + g_deg[n];
    for (int j = s0; j < s1; j++) {
        int a = g_adj[j];
        float nr = di * g_adn[j];
        float4 hv = *(const float4*)&g_h[(size_t)a * D + c];
        acc.x += hv.x * nr; acc.y += hv.y * nr;
        acc.z += hv.z * nr; acc.w += hv.w * nr;
    }
    float4 bb = *(const float4*)&b[c];
    acc.x += bb.x; acc.y += bb.y; acc.z += bb.z; acc.w += bb.w;
    if (relu) {
        acc.x = fmaxf(acc.x, 0.f); acc.y = fmaxf(acc.y, 0.f);
        acc.z = fmaxf(acc.z, 0.f); acc.w = fmaxf(acc.w, 0.f);
    }
    *(float4*)&g_x[(size_t)n * D + c] = acc;
}

// ================= per-edge MLP epilogue =================
__global__ void k_edge_pred(const int* __restrict__ ei,
                            const float* __restrict__ m1b,
                            const float* __restrict__ m2W,
                            const float* __restrict__ m2b,
                            float* __restrict__ out) {
    int gid = blockIdx.x * blockDim.x + threadIdx.x;
    int w = gid >> 5;
    int lane = gid & 31;
    if (w >= NE) return;
    int u = ei[w];
    int p = ei[NE + w];
    const float4* b1 = (const float4*)&g_h[(size_t)u * D];
    const float4* b2 = (const float4*)&g_h[(size_t)p * D];
    const float4* bias4 = (const float4*)m1b;
    const float4* w4 = (const float4*)m2W;
    float s = 0.f;
    #pragma unroll
    for (int i = 0; i < 2; i++) {
        int idx = lane + 32 * i;
        float4 a = b1[idx];
        float4 b = b2[idx];
        float4 bb = bias4[idx];
        float4 ww = w4[idx];
        s += fmaxf(a.x + b.x + bb.x, 0.f) * ww.x;
        s += fmaxf(a.y + b.y + bb.y, 0.f) * ww.y;
        s += fmaxf(a.z + b.z + bb.z, 0.f) * ww.z;
        s += fmaxf(a.w + b.w + bb.w, 0.f) * ww.w;
    }
    #pragma unroll
    for (int o = 16; o; o >>= 1) s += __shfl_down_sync(0xFFFFFFFFu, s, o);
    if (lane == 0) out[w] = s + m2b[0];
}

// ================= launch =================
extern "C" void kernel_launch(void* const* d_in, const int* in_sizes, int n_in,
                              void* d_out, int out_size) {
    const int*   ei   = (const int*)d_in[0];
    const float* uf   = (const float*)d_in[1];
    const float* pf   = (const float*)d_in[2];
    const float* uemb = (const float*)d_in[3];
    const float* pemb = (const float*)d_in[4];
    const float* uW   = (const float*)d_in[5];
    const float* ub   = (const float*)d_in[6];
    const float* pW   = (const float*)d_in[7];
    const float* pb   = (const float*)d_in[8];
    const float* c1W  = (const float*)d_in[9];
    const float* c1b  = (const float*)d_in[10];
    const float* c2W  = (const float*)d_in[11];
    const float* c2b  = (const float*)d_in[12];
    const float* m1W  = (const float*)d_in[13];
    const float* m1b  = (const float*)d_in[14];
    const float* m2W  = (const float*)d_in[15];
    const float* m2b  = (const float*)d_in[16];
    float* preds = (float*)d_out;

    float* xp;  float* hp;  float* wt;  int* degp; int* totp;
    cudaGetSymbolAddress((void**)&xp, g_x);
    cudaGetSymbolAddress((void**)&hp, g_h);
    cudaGetSymbolAddress((void**)&wt, g_wt);
    cudaGetSymbolAddress((void**)&degp, g_deg);
    cudaGetSymbolAddress((void**)&totp, g_total);

    cudaFuncSetAttribute(gemm_tc, cudaFuncAttributeMaxDynamicSharedMemorySize, GEMM_SMEM);

    // ---- CSR build ----
    cudaMemsetAsync(degp, 0, NN * sizeof(int), 0);
    cudaMemsetAsync(totp, 0, sizeof(int), 0);
    k_degree<<<(NE + 255) / 256, 256>>>(ei);
    k_offsets<<<(NN + 255) / 256, 256>>>();
    k_fill<<<(NE + 255) / 256, 256>>>(ei);

    // ---- transpose (+ tf32 pre-round) weights into g_wt ----
    dim3 tb(32, 8);
    k_transpose<<<dim3(8, 4),  tb>>>(uW,  wt + WT_U,  128, 256);
    k_transpose<<<dim3(8, 4),  tb>>>(pW,  wt + WT_P,  128, 256);
    k_transpose<<<dim3(8, 8),  tb>>>(c1W, wt + WT_C1, 256, 256);
    k_transpose<<<dim3(8, 8),  tb>>>(c2W, wt + WT_C2, 256, 256);
    k_transpose<<<dim3(8, 16), tb>>>(m1W, wt + WT_M1, 512, 256);

    dim3 gU((NU + 127) / 128, 2);
    dim3 gP((NP + 127) / 128, 2);
    dim3 gN((NN + 127) / 128, 2);
    const int nElem = (NN * 64 + 255) / 256;

    // input transforms: x = feats @ W + b + emb
    gemm_tc<<<gU, 256, GEMM_SMEM>>>(uf, wt + WT_U, 128, ub, uemb, xp, NU, 128);
    gemm_tc<<<gP, 256, GEMM_SMEM>>>(pf, wt + WT_P, 128, pb, pemb, xp + (size_t)NU * D, NP, 128);

    // conv1 (relu)
    gemm_tc<<<gN, 256, GEMM_SMEM>>>(xp, wt + WT_C1, 256, nullptr, nullptr, hp, NN, 256);
    k_gather<<<nElem, 256>>>(c1b, 1);

    // conv2 (no relu)
    gemm_tc<<<gN, 256, GEMM_SMEM>>>(xp, wt + WT_C2, 256, nullptr, nullptr, hp, NN, 256);
    k_gather<<<nElem, 256>>>(c2b, 0);

    // MLP factored through nodes: top half of m1W for users, bottom for products
    gemm_tc<<<gU, 256, GEMM_SMEM>>>(xp, wt + WT_M1, 512, nullptr, nullptr, hp, NU, 256);
    gemm_tc<<<gP, 256, GEMM_SMEM>>>(xp + (size_t)NU * D, wt + WT_M1 + 256, 512,
                                    nullptr, nullptr, hp + (size_t)NU * D, NP, 256);

    // per-edge scoring
    k_edge_pred<<<(NE * 32 + 255) / 256, 256>>>(ei, m1b, m2W, m2b, preds);
}

// round 8
// speedup vs baseline: 3.2306x; 1.0115x over previous
#include <cuda_runtime.h>
#include <cstdint>

#define NU 100000
#define NP 50000
#define NN 150000   // NU + NP
#define NE 250000
#define D  256

// ---------------- scratch (static device globals; no allocation) ----------------
__device__ float g_x[(size_t)NN * D];   // node features / conv output
__device__ float g_h[(size_t)NN * D];   // x @ W  (also MLP node-partials)
__device__ float g_dinv[NN];
__device__ int   g_deg[NN];
__device__ int   g_off[NN];
__device__ int   g_cur[NN];
__device__ int   g_total;
__device__ int   g_adj[2 * NE];
__device__ float g_adn[2 * NE];
// transposed (and tf32-pre-rounded) weights:
// uWt[256x128] pWt[256x128] c1Wt[256x256] c2Wt[256x256] m1Wt[256x512]
__device__ float g_wt[327680];
#define WT_U  0
#define WT_P  32768
#define WT_C1 65536
#define WT_C2 131072
#define WT_M1 196608

// ================= helpers =================
__device__ __forceinline__ uint32_t smem_u32(const void* p) {
    uint32_t a;
    asm("{ .reg .u64 t; cvta.to.shared.u64 t, %1; cvt.u32.u64 %0, t; }" : "=r"(a) : "l"(p));
    return a;
}
__device__ __forceinline__ uint32_t totf32(float x) {
    uint32_t u;
    asm("cvt.rna.tf32.f32 %0, %1;" : "=r"(u) : "f"(x));
    return u;
}
__device__ __forceinline__ uint32_t tf32r(uint32_t x) {
    return totf32(__uint_as_float(x));
}
#define SWZ(off) ((off) ^ (((off) >> 3) & 0x70))
#define LDSM_X4(r0, r1, r2, r3, addr) \
    asm volatile("ldmatrix.sync.aligned.m8n8.x4.shared.b16 {%0, %1, %2, %3}, [%4];" \
                 : "=r"(r0), "=r"(r1), "=r"(r2), "=r"(r3) : "r"(addr))
#define MMA_TF32(c, a0, a1, a2, a3, b0, b1) \
    asm volatile("mma.sync.aligned.m16n8k8.row.col.f32.tf32.tf32.f32 " \
                 "{%0, %1, %2, %3}, {%4, %5, %6, %7}, {%8, %9}, {%0, %1, %2, %3};" \
                 : "+f"((c)[0]), "+f"((c)[1]), "+f"((c)[2]), "+f"((c)[3]) \
                 : "r"(a0), "r"(a1), "r"(a2), "r"(a3), "r"(b0), "r"(b1))
#define CP_ASYNC16(dst, src, sz) \
    asm volatile("cp.async.cg.shared.global [%0], [%1], 16, %2;" \
                 :: "r"(dst), "l"(src), "r"(sz) : "memory")
#define CP_COMMIT() asm volatile("cp.async.commit_group;" ::: "memory")
#define CP_WAIT2()  asm volatile("cp.async.wait_group 2;" ::: "memory")

// ================= degree / CSR build =================
__global__ void k_degree(const int* __restrict__ ei) {
    int e = blockIdx.x * blockDim.x + threadIdx.x;
    if (e < NE) {
        atomicAdd(&g_deg[ei[e]], 1);
        atomicAdd(&g_deg[ei[NE + e]], 1);
    }
}
// offsets + dinv + cur-zero fused
__global__ void k_offsets() {
    int n = blockIdx.x * blockDim.x + threadIdx.x;
    int lane = threadIdx.x & 31;
    int d = (n < NN) ? g_deg[n] : 0;
    int incl = d;
    #pragma unroll
    for (int o = 1; o < 32; o <<= 1) {
        int t = __shfl_up_sync(0xFFFFFFFFu, incl, o);
        if (lane >= o) incl += t;
    }
    int excl = incl - d;
    int base = 0;
    if (lane == 31) base = atomicAdd(&g_total, incl);
    base = __shfl_sync(0xFFFFFFFFu, base, 31);
    if (n < NN) {
        g_off[n] = base + excl;
        g_cur[n] = 0;
        g_dinv[n] = rsqrtf((float)d + 1.0f);
    }
}
__global__ void k_fill(const int* __restrict__ ei) {
    int e = blockIdx.x * blockDim.x + threadIdx.x;
    if (e >= NE) return;
    int u = ei[e];
    int p = ei[NE + e];
    float du = g_dinv[u], dp = g_dinv[p];
    int idx = g_off[p] + atomicAdd(&g_cur[p], 1);
    g_adj[idx] = u;  g_adn[idx] = du;
    int idx2 = g_off[u] + atomicAdd(&g_cur[u], 1);
    g_adj[idx2] = p; g_adn[idx2] = dp;
}

// ========= weight transpose + tf32 pre-round: Wt[n][k] = tf32(W[k][n]) =========
__global__ void k_transpose(const float* __restrict__ W, float* __restrict__ Wt, int K, int N) {
    __shared__ float t[32][33];
    int bn = blockIdx.x * 32, bk = blockIdx.y * 32;
    #pragma unroll
    for (int i = 0; i < 4; i++) {
        int k = bk + threadIdx.y + i * 8, n = bn + threadIdx.x;
        if (k < K && n < N) t[threadIdx.y + i * 8][threadIdx.x] = W[(size_t)k * N + n];
    }
    __syncthreads();
    #pragma unroll
    for (int i = 0; i < 4; i++) {
        int n = bn + threadIdx.y + i * 8, k = bk + threadIdx.x;
        if (k < K && n < N)
            Wt[(size_t)n * K + k] =
                __uint_as_float(totf32(t[threadIdx.x][threadIdx.y + i * 8]));
    }
}

// ================= tf32 mma.sync GEMM body, cp.async 3-stage pipeline =================
// C[M,256] = A[M,K] @ Bt[colrange,K]^T (+bias)(+emb).  Bt row stride = ldb.
// Block tile 128x128x32, 8 warps (4 M x 2 N), warp tile 32x64 via m16n8k8.
#define NSTAGE 3
#define STAGE_BYTES 32768
#define GEMM_SMEM (NSTAGE * STAGE_BYTES)

__device__ __forceinline__ void gemm_body(const float* __restrict__ A,
                                          const float* __restrict__ Bt, int ldb,
                                          const float* __restrict__ bias,
                                          const float* __restrict__ emb,
                                          float* __restrict__ C,
                                          int M, int K, int blkx, int blky,
                                          uint32_t sb) {
    int tid = threadIdx.x;
    int lane = tid & 31;
    int wid = tid >> 5;
    int warpM = wid & 3;
    int warpN = wid >> 2;
    int rowBase = blkx * 128;
    int colBase = blky * 128;

    float acc[2][8][4];
    #pragma unroll
    for (int mt = 0; mt < 2; mt++)
        #pragma unroll
        for (int j = 0; j < 8; j++)
            #pragma unroll
            for (int q = 0; q < 4; q++) acc[mt][j][q] = 0.f;

    const int fr  = tid >> 3;
    const int fc4 = tid & 7;
    const float* aSrcBase = A  + (size_t)(rowBase + fr) * K + fc4 * 4;
    const float* bSrcBase = Bt + (size_t)(colBase + fr) * ldb + fc4 * 4;

    #define ISSUE_CHUNK(c)                                                         \
        {                                                                          \
            int k0 = (c) << 5;                                                     \
            uint32_t abase = sb + ((c) % NSTAGE) * STAGE_BYTES;                    \
            uint32_t bbase = abase + 16384;                                        \
            _Pragma("unroll")                                                      \
            for (int i = 0; i < 4; i++) {                                          \
                int r = fr + i * 32;                                               \
                uint32_t off = SWZ((uint32_t)(r * 128 + fc4 * 16));                \
                uint32_t asz = (rowBase + r < M) ? 16u : 0u;                       \
                CP_ASYNC16(abase + off, aSrcBase + (size_t)(i * 32) * K + k0, asz);\
                CP_ASYNC16(bbase + off, bSrcBase + (size_t)(i * 32) * ldb + k0, 16u);\
            }                                                                      \
        }

    const int arow = warpM * 32 + (lane & 15);
    const int achunkoff = (lane >> 4);
    const int brow = warpN * 64 + ((lane >> 4) << 3) + (lane & 7);
    const int bchunkoff = ((lane >> 3) & 1);

    const int CH = K >> 5;
    ISSUE_CHUNK(0); CP_COMMIT();
    if (CH > 1) { ISSUE_CHUNK(1); }
    CP_COMMIT();

    for (int ch = 0; ch < CH; ch++) {
        if (ch + NSTAGE - 1 < CH) { ISSUE_CHUNK(ch + NSTAGE - 1); }
        CP_COMMIT();
        CP_WAIT2();
        __syncthreads();

        uint32_t abase = sb + (ch % NSTAGE) * STAGE_BYTES;
        uint32_t bbase = abase + 16384;
        #pragma unroll
        for (int ks = 0; ks < 4; ks++) {
            uint32_t af[2][4];
            #pragma unroll
            for (int mt = 0; mt < 2; mt++) {
                int r = arow + mt * 16;
                uint32_t addr = abase + SWZ((uint32_t)(r * 128 + (2 * ks + achunkoff) * 16));
                LDSM_X4(af[mt][0], af[mt][1], af[mt][2], af[mt][3], addr);
                #pragma unroll
                for (int q = 0; q < 4; q++) af[mt][q] = tf32r(af[mt][q]);
            }
            uint32_t bf[4][4];
            #pragma unroll
            for (int jp = 0; jp < 4; jp++) {
                int r = brow + jp * 16;
                uint32_t addr = bbase + SWZ((uint32_t)(r * 128 + (2 * ks + bchunkoff) * 16));
                LDSM_X4(bf[jp][0], bf[jp][1], bf[jp][2], bf[jp][3], addr);
            }
            #pragma unroll
            for (int mt = 0; mt < 2; mt++)
                #pragma unroll
                for (int j = 0; j < 8; j++)
                    MMA_TF32(acc[mt][j], af[mt][0], af[mt][1], af[mt][2], af[mt][3],
                             bf[j >> 1][(j & 1) * 2], bf[j >> 1][(j & 1) * 2 + 1]);
        }
        __syncthreads();
    }

    #pragma unroll
    for (int mt = 0; mt < 2; mt++) {
        int r0 = rowBase + warpM * 32 + mt * 16 + (lane >> 2);
        int r1 = r0 + 8;
        #pragma unroll
        for (int j = 0; j < 8; j++) {
            int gc = colBase + warpN * 64 + j * 8 + (lane & 3) * 2;
            float2 v0 = make_float2(acc[mt][j][0], acc[mt][j][1]);
            float2 v1 = make_float2(acc[mt][j][2], acc[mt][j][3]);
            if (bias) {
                float2 bb = *(const float2*)&bias[gc];
                v0.x += bb.x; v0.y += bb.y;
                v1.x += bb.x; v1.y += bb.y;
            }
            if (r0 < M) {
                if (emb) {
                    float2 e0 = *(const float2*)&emb[(size_t)r0 * 256 + gc];
                    v0.x += e0.x; v0.y += e0.y;
                }
                *(float2*)&C[(size_t)r0 * 256 + gc] = v0;
            }
            if (r1 < M) {
                if (emb) {
                    float2 e1 = *(const float2*)&emb[(size_t)r1 * 256 + gc];
                    v1.x += e1.x; v1.y += e1.y;
                }
                *(float2*)&C[(size_t)r1 * 256 + gc] = v1;
            }
        }
    }
    #undef ISSUE_CHUNK
}

// single-segment GEMM (convs)
__global__ __launch_bounds__(256, 2) void gemm_tc(const float* __restrict__ A,
                                                  const float* __restrict__ Bt, int ldb,
                                                  float* __restrict__ C, int M, int K) {
    extern __shared__ char smem[];
    gemm_body(A, Bt, ldb, nullptr, nullptr, C, M, K, blockIdx.x, blockIdx.y,
              smem_u32(smem));
}

// dual-segment GEMM: blocks [0,split) -> segment 0, [split,...) -> segment 1.
// Same K for both segments.
__global__ __launch_bounds__(256, 2) void gemm_dual(
    const float* __restrict__ A0, const float* __restrict__ B0,
    const float* __restrict__ bias0, const float* __restrict__ emb0,
    float* __restrict__ C0, int M0,
    const float* __restrict__ A1, const float* __restrict__ B1,
    const float* __restrict__ bias1, const float* __restrict__ emb1,
    float* __restrict__ C1, int M1,
    int ldb, int K, int split) {
    extern __shared__ char smem[];
    uint32_t sb = smem_u32(smem);
    if ((int)blockIdx.x < split)
        gemm_body(A0, B0, ldb, bias0, emb0, C0, M0, K, blockIdx.x, blockIdx.y, sb);
    else
        gemm_body(A1, B1, ldb, bias1, emb1, C1, M1, K, blockIdx.x - split, blockIdx.y, sb);
}

// ================= fused GCN aggregation (CSR gather) =================
__global__ void k_gather(const float* __restrict__ b, int relu) {
    int i = blockIdx.x * blockDim.x + threadIdx.x;
    if (i >= NN * 64) return;
    int n = i >> 6;
    int c = (i & 63) << 2;
    float di = g_dinv[n];
    float s2 = di * di;
    float4 h = *(const float4*)&g_h[(size_t)n * D + c];
    float4 acc = make_float4(h.x * s2, h.y * s2, h.z * s2, h.w * s2);
    int s0 = g_off[n];
    int s1 = s0 + g_deg[n];
    for (int j = s0; j < s1; j++) {
        int a = g_adj[j];
        float nr = di * g_adn[j];
        float4 hv = *(const float4*)&g_h[(size_t)a * D + c];
        acc.x += hv.x * nr; acc.y += hv.y * nr;
        acc.z += hv.z * nr; acc.w += hv.w * nr;
    }
    float4 bb = *(const float4*)&b[c];
    acc.x += bb.x; acc.y += bb.y; acc.z += bb.z; acc.w += bb.w;
    if (relu) {
        acc.x = fmaxf(acc.x, 0.f); acc.y = fmaxf(acc.y, 0.f);
        acc.z = fmaxf(acc.z, 0.f); acc.w = fmaxf(acc.w, 0.f);
    }
    *(float4*)&g_x[(size_t)n * D + c] = acc;
}

// ================= per-edge MLP epilogue =================
__global__ void k_edge_pred(const int* __restrict__ ei,
                            const float* __restrict__ m1b,
                            const float* __restrict__ m2W,
                            const float* __restrict__ m2b,
                            float* __restrict__ out) {
    int gid = blockIdx.x * blockDim.x + threadIdx.x;
    int w = gid >> 5;
    int lane = gid & 31;
    if (w >= NE) return;
    int u = ei[w];
    int p = ei[NE + w];
    const float4* b1 = (const float4*)&g_h[(size_t)u * D];
    const float4* b2 = (const float4*)&g_h[(size_t)p * D];
    const float4* bias4 = (const float4*)m1b;
    const float4* w4 = (const float4*)m2W;
    float s = 0.f;
    #pragma unroll
    for (int i = 0; i < 2; i++) {
        int idx = lane + 32 * i;
        float4 a = b1[idx];
        float4 b = b2[idx];
        float4 bb = bias4[idx];
        float4 ww = w4[idx];
        s += fmaxf(a.x + b.x + bb.x, 0.f) * ww.x;
        s += fmaxf(a.y + b.y + bb.y, 0.f) * ww.y;
        s += fmaxf(a.z + b.z + bb.z, 0.f) * ww.z;
        s += fmaxf(a.w + b.w + bb.w, 0.f) * ww.w;
    }
    #pragma unroll
    for (int o = 16; o; o >>= 1) s += __shfl_down_sync(0xFFFFFFFFu, s, o);
    if (lane == 0) out[w] = s + m2b[0];
}

// ================= launch =================
extern "C" void kernel_launch(void* const* d_in, const int* in_sizes, int n_in,
                              void* d_out, int out_size) {
    const int*   ei   = (const int*)d_in[0];
    const float* uf   = (const float*)d_in[1];
    const float* pf   = (const float*)d_in[2];
    const float* uemb = (const float*)d_in[3];
    const float* pemb = (const float*)d_in[4];
    const float* uW   = (const float*)d_in[5];
    const float* ub   = (const float*)d_in[6];
    const float* pW   = (const float*)d_in[7];
    const float* pb   = (const float*)d_in[8];
    const float* c1W  = (const float*)d_in[9];
    const float* c1b  = (const float*)d_in[10];
    const float* c2W  = (const float*)d_in[11];
    const float* c2b  = (const float*)d_in[12];
    const float* m1W  = (const float*)d_in[13];
    const float* m1b  = (const float*)d_in[14];
    const float* m2W  = (const float*)d_in[15];
    const float* m2b  = (const float*)d_in[16];
    float* preds = (float*)d_out;

    float* xp;  float* hp;  float* wt;  int* degp; int* totp;
    cudaGetSymbolAddress((void**)&xp, g_x);
    cudaGetSymbolAddress((void**)&hp, g_h);
    cudaGetSymbolAddress((void**)&wt, g_wt);
    cudaGetSymbolAddress((void**)&degp, g_deg);
    cudaGetSymbolAddress((void**)&totp, g_total);

    // one-time host resources (no device memory)
    static cudaStream_t s2 = nullptr;
    static cudaEvent_t evFork = nullptr, evJoin = nullptr;
    static bool attrSet = false;
    if (!s2) {
        cudaStreamCreateWithFlags(&s2, cudaStreamNonBlocking);
        cudaEventCreateWithFlags(&evFork, cudaEventDisableTiming);
        cudaEventCreateWithFlags(&evJoin, cudaEventDisableTiming);
    }
    if (!attrSet) {
        cudaFuncSetAttribute(gemm_tc,   cudaFuncAttributeMaxDynamicSharedMemorySize, GEMM_SMEM);
        cudaFuncSetAttribute(gemm_dual, cudaFuncAttributeMaxDynamicSharedMemorySize, GEMM_SMEM);
        attrSet = true;
    }

    // ---- fork: CSR build on s2, concurrent with transposes + input GEMMs ----
    cudaEventRecord(evFork, 0);
    cudaStreamWaitEvent(s2, evFork, 0);
    cudaMemsetAsync(degp, 0, NN * sizeof(int), s2);
    cudaMemsetAsync(totp, 0, sizeof(int), s2);
    k_degree<<<(NE + 255) / 256, 256, 0, s2>>>(ei);
    k_offsets<<<(NN + 255) / 256, 256, 0, s2>>>();
    k_fill<<<(NE + 255) / 256, 256, 0, s2>>>(ei);
    cudaEventRecord(evJoin, s2);

    // ---- main stream: transposes (+ tf32 pre-round) ----
    dim3 tb(32, 8);
    k_transpose<<<dim3(8, 4),  tb>>>(uW,  wt + WT_U,  128, 256);
    k_transpose<<<dim3(8, 4),  tb>>>(pW,  wt + WT_P,  128, 256);
    k_transpose<<<dim3(8, 8),  tb>>>(c1W, wt + WT_C1, 256, 256);
    k_transpose<<<dim3(8, 8),  tb>>>(c2W, wt + WT_C2, 256, 256);
    k_transpose<<<dim3(8, 16), tb>>>(m1W, wt + WT_M1, 512, 256);

    const int gU = (NU + 127) / 128;   // 782
    const int gP = (NP + 127) / 128;   // 391
    const int gN = (NN + 127) / 128;   // 1172
    const int nElem = (NN * 64 + 255) / 256;

    // input transforms (merged U+P): x = feats @ W + b + emb
    gemm_dual<<<dim3(gU + gP, 2), 256, GEMM_SMEM>>>(
        uf, wt + WT_U, ub, uemb, xp, NU,
        pf, wt + WT_P, pb, pemb, xp + (size_t)NU * D, NP,
        128, 128, gU);

    // conv1 (relu) — gather needs CSR: join s2 before it
    gemm_tc<<<dim3(gN, 2), 256, GEMM_SMEM>>>(xp, wt + WT_C1, 256, hp, NN, 256);
    cudaStreamWaitEvent(0, evJoin, 0);
    k_gather<<<nElem, 256>>>(c1b, 1);

    // conv2 (no relu)
    gemm_tc<<<dim3(gN, 2), 256, GEMM_SMEM>>>(xp, wt + WT_C2, 256, hp, NN, 256);
    k_gather<<<nElem, 256>>>(c2b, 0);

    // MLP factored through nodes (merged U+P)
    gemm_dual<<<dim3(gU + gP, 2), 256, GEMM_SMEM>>>(
        xp, wt + WT_M1, nullptr, nullptr, hp, NU,
        xp + (size_t)NU * D, wt + WT_M1 + 256, nullptr, nullptr, hp + (size_t)NU * D, NP,
        512, 256, gU);

    // per-edge scoring
    k_edge_pred<<<(NE * 32 + 255) / 256, 256>>>(ei, m1b, m2W, m2b, preds);
}

// round 11
// speedup vs baseline: 3.3846x; 1.0477x over previous
#include <cuda_runtime.h>
#include <cstdint>

#define NU 100000
#define NP 50000
#define NN 150000   // NU + NP
#define NE 250000
#define D  256

// ---------------- scratch (static device globals; no allocation) ----------------
__device__ float g_x[(size_t)NN * D];   // node features / conv output
__device__ float g_h[(size_t)NN * D];   // x @ W (dinv-scaled for convs) / MLP partials
__device__ float g_dinv[NN];
__device__ int   g_deg[NN];
__device__ int   g_off[NN];
__device__ int   g_cur[NN];
__device__ int   g_total;
__device__ int   g_adj[2 * NE];         // neighbor node id per CSR slot
__device__ int   g_aid[2 * NE];         // edge id per CSR slot
// transposed (and tf32-pre-rounded) weights
__device__ float g_wt[327680];
#define WT_U  0
#define WT_P  32768
#define WT_C1 65536
#define WT_C2 131072
#define WT_M1 196608

// ================= helpers =================
__device__ __forceinline__ uint32_t smem_u32(const void* p) {
    uint32_t a;
    asm("{ .reg .u64 t; cvta.to.shared.u64 t, %1; cvt.u32.u64 %0, t; }" : "=r"(a) : "l"(p));
    return a;
}
__device__ __forceinline__ uint32_t totf32(float x) {
    uint32_t u;
    asm("cvt.rna.tf32.f32 %0, %1;" : "=r"(u) : "f"(x));
    return u;
}
__device__ __forceinline__ uint32_t tf32r(uint32_t x) {
    return totf32(__uint_as_float(x));
}
#define SWZ(off) ((off) ^ (((off) >> 3) & 0x70))
#define LDSM_X4(r0, r1, r2, r3, addr) \
    asm volatile("ldmatrix.sync.aligned.m8n8.x4.shared.b16 {%0, %1, %2, %3}, [%4];" \
                 : "=r"(r0), "=r"(r1), "=r"(r2), "=r"(r3) : "r"(addr))
#define MMA_TF32(c, a0, a1, a2, a3, b0, b1) \
    asm volatile("mma.sync.aligned.m16n8k8.row.col.f32.tf32.tf32.f32 " \
                 "{%0, %1, %2, %3}, {%4, %5, %6, %7}, {%8, %9}, {%0, %1, %2, %3};" \
                 : "+f"((c)[0]), "+f"((c)[1]), "+f"((c)[2]), "+f"((c)[3]) \
                 : "r"(a0), "r"(a1), "r"(a2), "r"(a3), "r"(b0), "r"(b1))
#define CP_ASYNC16(dst, src, sz) \
    asm volatile("cp.async.cg.shared.global [%0], [%1], 16, %2;" \
                 :: "r"(dst), "l"(src), "r"(sz) : "memory")
#define CP_COMMIT() asm volatile("cp.async.commit_group;" ::: "memory")
#define CP_WAIT1()  asm volatile("cp.async.wait_group 1;" ::: "memory")

// ================= degree / CSR build =================
__global__ void k_degree(const int* __restrict__ ei) {
    int e = blockIdx.x * blockDim.x + threadIdx.x;
    if (e < NE) {
        atomicAdd(&g_deg[ei[e]], 1);
        atomicAdd(&g_deg[ei[NE + e]], 1);
    }
}
// offsets + dinv + cur-zero fused
__global__ void k_offsets() {
    int n = blockIdx.x * blockDim.x + threadIdx.x;
    int lane = threadIdx.x & 31;
    int d = (n < NN) ? g_deg[n] : 0;
    int incl = d;
    #pragma unroll
    for (int o = 1; o < 32; o <<= 1) {
        int t = __shfl_up_sync(0xFFFFFFFFu, incl, o);
        if (lane >= o) incl += t;
    }
    int excl = incl - d;
    int base = 0;
    if (lane == 31) base = atomicAdd(&g_total, incl);
    base = __shfl_sync(0xFFFFFFFFu, base, 31);
    if (n < NN) {
        g_off[n] = base + excl;
        g_cur[n] = 0;
        g_dinv[n] = rsqrtf((float)d + 1.0f);
    }
}
__global__ void k_fill(const int* __restrict__ ei) {
    int e = blockIdx.x * blockDim.x + threadIdx.x;
    if (e >= NE) return;
    int u = ei[e];
    int p = ei[NE + e];
    int idx = g_off[p] + atomicAdd(&g_cur[p], 1);
    g_adj[idx] = u;  g_aid[idx] = e;
    int idx2 = g_off[u] + atomicAdd(&g_cur[u], 1);
    g_adj[idx2] = p; g_aid[idx2] = e;
}

// ========= weight transpose + tf32 pre-round: Wt[n][k] = tf32(W[k][n]) =========
__global__ void k_transpose(const float* __restrict__ W, float* __restrict__ Wt, int K, int N) {
    __shared__ float t[32][33];
    int bn = blockIdx.x * 32, bk = blockIdx.y * 32;
    #pragma unroll
    for (int i = 0; i < 4; i++) {
        int k = bk + threadIdx.y + i * 8, n = bn + threadIdx.x;
        if (k < K && n < N) t[threadIdx.y + i * 8][threadIdx.x] = W[(size_t)k * N + n];
    }
    __syncthreads();
    #pragma unroll
    for (int i = 0; i < 4; i++) {
        int n = bn + threadIdx.y + i * 8, k = bk + threadIdx.x;
        if (k < K && n < N)
            Wt[(size_t)n * K + k] =
                __uint_as_float(totf32(t[threadIdx.x][threadIdx.y + i * 8]));
    }
}

// ================= tf32 mma.sync GEMM body, cp.async 3-stage, 1 sync/chunk =======
// Commit discipline: exactly ONE commit_group per iteration (empty groups legal),
// so at iter ch committed groups are 0..ch+1 and wait_group 1 guarantees chunk ch
// is fully resident — including the tail chunks.
#define NSTAGE 3
#define STAGE_BYTES 32768
#define GEMM_SMEM (NSTAGE * STAGE_BYTES)

__device__ __forceinline__ void gemm_body(const float* __restrict__ A,
                                          const float* __restrict__ Bt, int ldb,
                                          const float* __restrict__ bias,
                                          const float* __restrict__ emb,
                                          const float* __restrict__ rowscale,
                                          float* __restrict__ C,
                                          int M, int K, int blkx, int blky,
                                          uint32_t sb) {
    int tid = threadIdx.x;
    int lane = tid & 31;
    int wid = tid >> 5;
    int warpM = wid & 3;
    int warpN = wid >> 2;
    int rowBase = blkx * 128;
    int colBase = blky * 128;

    float acc[2][8][4];
    #pragma unroll
    for (int mt = 0; mt < 2; mt++)
        #pragma unroll
        for (int j = 0; j < 8; j++)
            #pragma unroll
            for (int q = 0; q < 4; q++) acc[mt][j][q] = 0.f;

    const int fr  = tid >> 3;
    const int fc4 = tid & 7;
    const float* aSrcBase = A  + (size_t)(rowBase + fr) * K + fc4 * 4;
    const float* bSrcBase = Bt + (size_t)(colBase + fr) * ldb + fc4 * 4;

    #define ISSUE_CHUNK(c)                                                         \
        {                                                                          \
            int k0 = (c) << 5;                                                     \
            uint32_t abase = sb + ((c) % NSTAGE) * STAGE_BYTES;                    \
            uint32_t bbase = abase + 16384;                                        \
            _Pragma("unroll")                                                      \
            for (int i = 0; i < 4; i++) {                                          \
                int r = fr + i * 32;                                               \
                uint32_t off = SWZ((uint32_t)(r * 128 + fc4 * 16));                \
                uint32_t asz = (rowBase + r < M) ? 16u : 0u;                       \
                CP_ASYNC16(abase + off, aSrcBase + (size_t)(i * 32) * K + k0, asz);\
                CP_ASYNC16(bbase + off, bSrcBase + (size_t)(i * 32) * ldb + k0, 16u);\
            }                                                                      \
        }

    const int arow = warpM * 32 + (lane & 15);
    const int achunkoff = (lane >> 4);
    const int brow = warpN * 64 + ((lane >> 4) << 3) + (lane & 7);
    const int bchunkoff = ((lane >> 3) & 1);

    const int CH = K >> 5;
    // prologue: groups 0 (chunk 0) and 1 (chunk 1)
    ISSUE_CHUNK(0); CP_COMMIT();
    if (CH > 1) { ISSUE_CHUNK(1); }
    CP_COMMIT();

    for (int ch = 0; ch < CH; ch++) {
        CP_WAIT1();            // groups <= ch complete -> chunk ch resident
        __syncthreads();       // all warps done reading stage (ch+NSTAGE-1)%NSTAGE's prior tenant
        if (ch + NSTAGE - 1 < CH) { ISSUE_CHUNK(ch + NSTAGE - 1); }
        CP_COMMIT();           // UNCONDITIONAL: group ch+2 (possibly empty)

        uint32_t abase = sb + (ch % NSTAGE) * STAGE_BYTES;
        uint32_t bbase = abase + 16384;
        #pragma unroll
        for (int ks = 0; ks < 4; ks++) {
            uint32_t af[2][4];
            #pragma unroll
            for (int mt = 0; mt < 2; mt++) {
                int r = arow + mt * 16;
                uint32_t addr = abase + SWZ((uint32_t)(r * 128 + (2 * ks + achunkoff) * 16));
                LDSM_X4(af[mt][0], af[mt][1], af[mt][2], af[mt][3], addr);
                #pragma unroll
                for (int q = 0; q < 4; q++) af[mt][q] = tf32r(af[mt][q]);
            }
            uint32_t bf[4][4];
            #pragma unroll
            for (int jp = 0; jp < 4; jp++) {
                int r = brow + jp * 16;
                uint32_t addr = bbase + SWZ((uint32_t)(r * 128 + (2 * ks + bchunkoff) * 16));
                LDSM_X4(bf[jp][0], bf[jp][1], bf[jp][2], bf[jp][3], addr);
            }
            #pragma unroll
            for (int mt = 0; mt < 2; mt++)
                #pragma unroll
                for (int j = 0; j < 8; j++)
                    MMA_TF32(acc[mt][j], af[mt][0], af[mt][1], af[mt][2], af[mt][3],
                             bf[j >> 1][(j & 1) * 2], bf[j >> 1][(j & 1) * 2 + 1]);
        }
    }

    #pragma unroll
    for (int mt = 0; mt < 2; mt++) {
        int r0 = rowBase + warpM * 32 + mt * 16 + (lane >> 2);
        int r1 = r0 + 8;
        float s0 = (rowscale && r0 < M) ? rowscale[r0] : 1.f;
        float s1 = (rowscale && r1 < M) ? rowscale[r1] : 1.f;
        #pragma unroll
        for (int j = 0; j < 8; j++) {
            int gc = colBase + warpN * 64 + j * 8 + (lane & 3) * 2;
            float2 v0 = make_float2(acc[mt][j][0] * s0, acc[mt][j][1] * s0);
            float2 v1 = make_float2(acc[mt][j][2] * s1, acc[mt][j][3] * s1);
            if (bias) {
                float2 bb = *(const float2*)&bias[gc];
                v0.x += bb.x; v0.y += bb.y;
                v1.x += bb.x; v1.y += bb.y;
            }
            if (r0 < M) {
                if (emb) {
                    float2 e0 = *(const float2*)&emb[(size_t)r0 * 256 + gc];
                    v0.x += e0.x; v0.y += e0.y;
                }
                *(float2*)&C[(size_t)r0 * 256 + gc] = v0;
            }
            if (r1 < M) {
                if (emb) {
                    float2 e1 = *(const float2*)&emb[(size_t)r1 * 256 + gc];
                    v1.x += e1.x; v1.y += e1.y;
                }
                *(float2*)&C[(size_t)r1 * 256 + gc] = v1;
            }
        }
    }
    #undef ISSUE_CHUNK
}

// single-segment GEMM (convs; rowscale = dinv)
__global__ __launch_bounds__(256, 2) void gemm_tc(const float* __restrict__ A,
                                                  const float* __restrict__ Bt, int ldb,
                                                  const float* __restrict__ rowscale,
                                                  float* __restrict__ C, int M, int K) {
    extern __shared__ char smem[];
    gemm_body(A, Bt, ldb, nullptr, nullptr, rowscale, C, M, K,
              blockIdx.x, blockIdx.y, smem_u32(smem));
}

// dual-segment GEMM: blocks [0,split) -> segment 0, rest -> segment 1.
__global__ __launch_bounds__(256, 2) void gemm_dual(
    const float* __restrict__ A0, const float* __restrict__ B0,
    const float* __restrict__ bias0, const float* __restrict__ emb0,
    float* __restrict__ C0, int M0,
    const float* __restrict__ A1, const float* __restrict__ B1,
    const float* __restrict__ bias1, const float* __restrict__ emb1,
    float* __restrict__ C1, int M1,
    int ldb, int K, int split) {
    extern __shared__ char smem[];
    uint32_t sb = smem_u32(smem);
    if ((int)blockIdx.x < split)
        gemm_body(A0, B0, ldb, bias0, emb0, nullptr, C0, M0, K, blockIdx.x, blockIdx.y, sb);
    else
        gemm_body(A1, B1, ldb, bias1, emb1, nullptr, C1, M1, K, blockIdx.x - split, blockIdx.y, sb);
}

// ================= fused GCN aggregation (CSR row-sum of h_scaled) =================
// g_h holds h_scaled = h * dinv[row].  out[n] = (sum_nbr + self) * dinv[n] + b.
__global__ void k_gather(const float* __restrict__ b, int relu) {
    int i = blockIdx.x * blockDim.x + threadIdx.x;
    if (i >= NN * 64) return;
    int n = i >> 6;
    int c = (i & 63) << 2;
    float di = g_dinv[n];
    float4 acc = *(const float4*)&g_h[(size_t)n * D + c];   // self (scaled)
    int s0 = g_off[n];
    int s1 = s0 + g_deg[n];
    for (int j = s0; j < s1; j++) {
        int a = g_adj[j];
        float4 hv = *(const float4*)&g_h[(size_t)a * D + c];
        acc.x += hv.x; acc.y += hv.y; acc.z += hv.z; acc.w += hv.w;
    }
    float4 bb = *(const float4*)&b[c];
    acc.x = acc.x * di + bb.x; acc.y = acc.y * di + bb.y;
    acc.z = acc.z * di + bb.z; acc.w = acc.w * di + bb.w;
    if (relu) {
        acc.x = fmaxf(acc.x, 0.f); acc.y = fmaxf(acc.y, 0.f);
        acc.z = fmaxf(acc.z, 0.f); acc.w = fmaxf(acc.w, 0.f);
    }
    *(float4*)&g_x[(size_t)n * D + c] = acc;
}

// ================= per-edge MLP, user-ordered (warp per user) =================
// hu + bias + m2W hoisted to registers; per edge only the product row is read.
__global__ void k_edge_pred_user(const float* __restrict__ m1b,
                                 const float* __restrict__ m2W,
                                 const float* __restrict__ m2b,
                                 float* __restrict__ out) {
    int gid = blockIdx.x * blockDim.x + threadIdx.x;
    int u = gid >> 5;
    int lane = gid & 31;
    if (u >= NU) return;
    int dg = g_deg[u];
    if (dg == 0) return;
    int s0 = g_off[u];

    const float4* hu4 = (const float4*)&g_h[(size_t)u * D];
    float4 a0 = hu4[lane];
    float4 a1 = hu4[lane + 32];
    float4 bb0 = ((const float4*)m1b)[lane];
    float4 bb1 = ((const float4*)m1b)[lane + 32];
    a0.x += bb0.x; a0.y += bb0.y; a0.z += bb0.z; a0.w += bb0.w;
    a1.x += bb1.x; a1.y += bb1.y; a1.z += bb1.z; a1.w += bb1.w;
    float4 w0 = ((const float4*)m2W)[lane];
    float4 w1 = ((const float4*)m2W)[lane + 32];
    float m2bb = m2b[0];

    for (int j = s0; j < s0 + dg; j++) {
        int p = g_adj[j];
        int e = g_aid[j];
        const float4* hp4 = (const float4*)&g_h[(size_t)p * D];
        float4 b0 = hp4[lane];
        float4 b1 = hp4[lane + 32];
        float s = fmaxf(a0.x + b0.x, 0.f) * w0.x
                + fmaxf(a0.y + b0.y, 0.f) * w0.y
                + fmaxf(a0.z + b0.z, 0.f) * w0.z
                + fmaxf(a0.w + b0.w, 0.f) * w0.w
                + fmaxf(a1.x + b1.x, 0.f) * w1.x
                + fmaxf(a1.y + b1.y, 0.f) * w1.y
                + fmaxf(a1.z + b1.z, 0.f) * w1.z
                + fmaxf(a1.w + b1.w, 0.f) * w1.w;
        #pragma unroll
        for (int o = 16; o; o >>= 1) s += __shfl_down_sync(0xFFFFFFFFu, s, o);
        if (lane == 0) out[e] = s + m2bb;
    }
}

// ================= launch =================
extern "C" void kernel_launch(void* const* d_in, const int* in_sizes, int n_in,
                              void* d_out, int out_size) {
    const int*   ei   = (const int*)d_in[0];
    const float* uf   = (const float*)d_in[1];
    const float* pf   = (const float*)d_in[2];
    const float* uemb = (const float*)d_in[3];
    const float* pemb = (const float*)d_in[4];
    const float* uW   = (const float*)d_in[5];
    const float* ub   = (const float*)d_in[6];
    const float* pW   = (const float*)d_in[7];
    const float* pb   = (const float*)d_in[8];
    const float* c1W  = (const float*)d_in[9];
    const float* c1b  = (const float*)d_in[10];
    const float* c2W  = (const float*)d_in[11];
    const float* c2b  = (const float*)d_in[12];
    const float* m1W  = (const float*)d_in[13];
    const float* m1b  = (const float*)d_in[14];
    const float* m2W  = (const float*)d_in[15];
    const float* m2b  = (const float*)d_in[16];
    float* preds = (float*)d_out;

    float* xp;  float* hp;  float* wt;  float* dv;  int* degp; int* totp;
    cudaGetSymbolAddress((void**)&xp, g_x);
    cudaGetSymbolAddress((void**)&hp, g_h);
    cudaGetSymbolAddress((void**)&wt, g_wt);
    cudaGetSymbolAddress((void**)&dv, g_dinv);
    cudaGetSymbolAddress((void**)&degp, g_deg);
    cudaGetSymbolAddress((void**)&totp, g_total);

    static cudaStream_t s2 = nullptr;
    static cudaEvent_t evFork = nullptr, evJoin = nullptr;
    static bool attrSet = false;
    if (!s2) {
        cudaStreamCreateWithFlags(&s2, cudaStreamNonBlocking);
        cudaEventCreateWithFlags(&evFork, cudaEventDisableTiming);
        cudaEventCreateWithFlags(&evJoin, cudaEventDisableTiming);
    }
    if (!attrSet) {
        cudaFuncSetAttribute(gemm_tc,   cudaFuncAttributeMaxDynamicSharedMemorySize, GEMM_SMEM);
        cudaFuncSetAttribute(gemm_dual, cudaFuncAttributeMaxDynamicSharedMemorySize, GEMM_SMEM);
        attrSet = true;
    }

    // ---- fork: CSR build on s2 ----
    cudaEventRecord(evFork, 0);
    cudaStreamWaitEvent(s2, evFork, 0);
    cudaMemsetAsync(degp, 0, NN * sizeof(int), s2);
    cudaMemsetAsync(totp, 0, sizeof(int), s2);
    k_degree<<<(NE + 255) / 256, 256, 0, s2>>>(ei);
    k_offsets<<<(NN + 255) / 256, 256, 0, s2>>>();
    k_fill<<<(NE + 255) / 256, 256, 0, s2>>>(ei);
    cudaEventRecord(evJoin, s2);

    // ---- main stream: transposes ----
    dim3 tb(32, 8);
    k_transpose<<<dim3(8, 4),  tb>>>(uW,  wt + WT_U,  128, 256);
    k_transpose<<<dim3(8, 4),  tb>>>(pW,  wt + WT_P,  128, 256);
    k_transpose<<<dim3(8, 8),  tb>>>(c1W, wt + WT_C1, 256, 256);
    k_transpose<<<dim3(8, 8),  tb>>>(c2W, wt + WT_C2, 256, 256);
    k_transpose<<<dim3(8, 16), tb>>>(m1W, wt + WT_M1, 512, 256);

    const int gU = (NU + 127) / 128;
    const int gP = (NP + 127) / 128;
    const int gN = (NN + 127) / 128;
    const int nElem = (NN * 64 + 255) / 256;

    // input transforms (merged U+P): x = feats @ W + b + emb
    gemm_dual<<<dim3(gU + gP, 2), 256, GEMM_SMEM>>>(
        uf, wt + WT_U, ub, uemb, xp, NU,
        pf, wt + WT_P, pb, pemb, xp + (size_t)NU * D, NP,
        128, 128, gU);

    // conv1 (relu): GEMM writes h*dinv ; epilogue + gather need dinv/CSR from s2
    cudaStreamWaitEvent(0, evJoin, 0);
    gemm_tc<<<dim3(gN, 2), 256, GEMM_SMEM>>>(xp, wt + WT_C1, 256, dv, hp, NN, 256);
    k_gather<<<nElem, 256>>>(c1b, 1);

    // conv2 (no relu)
    gemm_tc<<<dim3(gN, 2), 256, GEMM_SMEM>>>(xp, wt + WT_C2, 256, dv, hp, NN, 256);
    k_gather<<<nElem, 256>>>(c2b, 0);

    // MLP factored through nodes (merged U+P, unscaled)
    gemm_dual<<<dim3(gU + gP, 2), 256, GEMM_SMEM>>>(
        xp, wt + WT_M1, nullptr, nullptr, hp, NU,
        xp + (size_t)NU * D, wt + WT_M1 + 256, nullptr, nullptr, hp + (size_t)NU * D, NP,
        512, 256, gU);

    // per-edge scoring, user-ordered
    k_edge_pred_user<<<(NU * 32 + 255) / 256, 256>>>(m1b, m2W, m2b, preds);
}

// round 13
// speedup vs baseline: 3.5769x; 1.0568x over previous
#include <cuda_runtime.h>
#include <cstdint>

#define NU 100000
#define NP 50000
#define NN 150000   // NU + NP
#define NE 250000
#define D  256

// ---------------- scratch (static device globals; no allocation) ----------------
__device__ float g_x[(size_t)NN * D];   // conv input chain (tf32-rounded at write)
__device__ float g_h[(size_t)NN * D];   // x @ W (dinv-scaled for convs) / MLP partials
__device__ float g_dinv[NN];
__device__ int   g_deg[NN];
__device__ int   g_off[NN];
__device__ int   g_cur[NN];
__device__ int   g_total;
__device__ int   g_adj[2 * NE];         // neighbor node id per CSR slot
__device__ int   g_aid[2 * NE];         // edge id per CSR slot
// transposed (and tf32-pre-rounded) weights
__device__ float g_wt[327680];
#define WT_U  0
#define WT_P  32768
#define WT_C1 65536
#define WT_C2 131072
#define WT_M1 196608

// ================= helpers =================
__device__ __forceinline__ uint32_t smem_u32(const void* p) {
    uint32_t a;
    asm("{ .reg .u64 t; cvta.to.shared.u64 t, %1; cvt.u32.u64 %0, t; }" : "=r"(a) : "l"(p));
    return a;
}
__device__ __forceinline__ uint32_t totf32(float x) {
    uint32_t u;
    asm("cvt.rna.tf32.f32 %0, %1;" : "=r"(u) : "f"(x));
    return u;
}
__device__ __forceinline__ uint32_t tf32r(uint32_t x) {
    return totf32(__uint_as_float(x));
}
__device__ __forceinline__ float tf32f(float x) {
    return __uint_as_float(totf32(x));
}
#define SWZ(off) ((off) ^ (((off) >> 3) & 0x70))
#define LDSM_X4(r0, r1, r2, r3, addr) \
    asm volatile("ldmatrix.sync.aligned.m8n8.x4.shared.b16 {%0, %1, %2, %3}, [%4];" \
                 : "=r"(r0), "=r"(r1), "=r"(r2), "=r"(r3) : "r"(addr))
#define MMA_TF32(c, a0, a1, a2, a3, b0, b1) \
    asm volatile("mma.sync.aligned.m16n8k8.row.col.f32.tf32.tf32.f32 " \
                 "{%0, %1, %2, %3}, {%4, %5, %6, %7}, {%8, %9}, {%0, %1, %2, %3};" \
                 : "+f"((c)[0]), "+f"((c)[1]), "+f"((c)[2]), "+f"((c)[3]) \
                 : "r"(a0), "r"(a1), "r"(a2), "r"(a3), "r"(b0), "r"(b1))
#define CP_ASYNC16(dst, src, sz) \
    asm volatile("cp.async.cg.shared.global [%0], [%1], 16, %2;" \
                 :: "r"(dst), "l"(src), "r"(sz) : "memory")
#define CP_COMMIT() asm volatile("cp.async.commit_group;" ::: "memory")
#define CP_WAIT1()  asm volatile("cp.async.wait_group 1;" ::: "memory")

// ================= degree / CSR build =================
__global__ void k_degree(const int* __restrict__ ei) {
    int e = blockIdx.x * blockDim.x + threadIdx.x;
    if (e < NE) {
        atomicAdd(&g_deg[ei[e]], 1);
        atomicAdd(&g_deg[ei[NE + e]], 1);
    }
}
// offsets + dinv + cur-zero fused
__global__ void k_offsets() {
    int n = blockIdx.x * blockDim.x + threadIdx.x;
    int lane = threadIdx.x & 31;
    int d = (n < NN) ? g_deg[n] : 0;
    int incl = d;
    #pragma unroll
    for (int o = 1; o < 32; o <<= 1) {
        int t = __shfl_up_sync(0xFFFFFFFFu, incl, o);
        if (lane >= o) incl += t;
    }
    int excl = incl - d;
    int base = 0;
    if (lane == 31) base = atomicAdd(&g_total, incl);
    base = __shfl_sync(0xFFFFFFFFu, base, 31);
    if (n < NN) {
        g_off[n] = base + excl;
        g_cur[n] = 0;
        g_dinv[n] = rsqrtf((float)d + 1.0f);
    }
}
__global__ void k_fill(const int* __restrict__ ei) {
    int e = blockIdx.x * blockDim.x + threadIdx.x;
    if (e >= NE) return;
    int u = ei[e];
    int p = ei[NE + e];
    int idx = g_off[p] + atomicAdd(&g_cur[p], 1);
    g_adj[idx] = u;  g_aid[idx] = e;
    int idx2 = g_off[u] + atomicAdd(&g_cur[u], 1);
    g_adj[idx2] = p; g_aid[idx2] = e;
}

// ========= weight transpose + tf32 pre-round: Wt[n][k] = tf32(W[k][n]) =========
__global__ void k_transpose(const float* __restrict__ W, float* __restrict__ Wt, int K, int N) {
    __shared__ float t[32][33];
    int bn = blockIdx.x * 32, bk = blockIdx.y * 32;
    #pragma unroll
    for (int i = 0; i < 4; i++) {
        int k = bk + threadIdx.y + i * 8, n = bn + threadIdx.x;
        if (k < K && n < N) t[threadIdx.y + i * 8][threadIdx.x] = W[(size_t)k * N + n];
    }
    __syncthreads();
    #pragma unroll
    for (int i = 0; i < 4; i++) {
        int n = bn + threadIdx.y + i * 8, k = bk + threadIdx.x;
        if (k < K && n < N)
            Wt[(size_t)n * K + k] = tf32f(t[threadIdx.x][threadIdx.y + i * 8]);
    }
}

// ================= tf32 mma.sync GEMM body, cp.async 3-stage, 1 sync/chunk =======
// ROUND_A: tf32-round A fragments after ldmatrix (only needed when A source is
//          raw fp32; our own tensors are pre-rounded at their producer).
// ROUND_OUT: tf32-round epilogue output (when the only consumer is another GEMM's
//          A operand) — single rounding either way, numerically identical.
// Commit discipline: exactly ONE commit_group per iteration (empty groups legal).
#define NSTAGE 3
#define STAGE_BYTES 32768
#define GEMM_SMEM (NSTAGE * STAGE_BYTES)

template<bool ROUND_A, bool ROUND_OUT>
__device__ __forceinline__ void gemm_body(const float* __restrict__ A,
                                          const float* __restrict__ Bt, int ldb,
                                          const float* __restrict__ bias,
                                          const float* __restrict__ emb,
                                          const float* __restrict__ rowscale,
                                          float* __restrict__ C,
                                          int M, int K, int blkx, int blky,
                                          uint32_t sb) {
    int tid = threadIdx.x;
    int lane = tid & 31;
    int wid = tid >> 5;
    int warpM = wid & 3;
    int warpN = wid >> 2;
    int rowBase = blkx * 128;
    int colBase = blky * 128;

    float acc[2][8][4];
    #pragma unroll
    for (int mt = 0; mt < 2; mt++)
        #pragma unroll
        for (int j = 0; j < 8; j++)
            #pragma unroll
            for (int q = 0; q < 4; q++) acc[mt][j][q] = 0.f;

    const int fr  = tid >> 3;
    const int fc4 = tid & 7;
    const float* aSrcBase = A  + (size_t)(rowBase + fr) * K + fc4 * 4;
    const float* bSrcBase = Bt + (size_t)(colBase + fr) * ldb + fc4 * 4;

    #define ISSUE_CHUNK(c)                                                         \
        {                                                                          \
            int k0 = (c) << 5;                                                     \
            uint32_t abase = sb + ((c) % NSTAGE) * STAGE_BYTES;                    \
            uint32_t bbase = abase + 16384;                                        \
            _Pragma("unroll")                                                      \
            for (int i = 0; i < 4; i++) {                                          \
                int r = fr + i * 32;                                               \
                uint32_t off = SWZ((uint32_t)(r * 128 + fc4 * 16));                \
                uint32_t asz = (rowBase + r < M) ? 16u : 0u;                       \
                CP_ASYNC16(abase + off, aSrcBase + (size_t)(i * 32) * K + k0, asz);\
                CP_ASYNC16(bbase + off, bSrcBase + (size_t)(i * 32) * ldb + k0, 16u);\
            }                                                                      \
        }

    const int arow = warpM * 32 + (lane & 15);
    const int achunkoff = (lane >> 4);
    const int brow = warpN * 64 + ((lane >> 4) << 3) + (lane & 7);
    const int bchunkoff = ((lane >> 3) & 1);

    const int CH = K >> 5;
    ISSUE_CHUNK(0); CP_COMMIT();
    if (CH > 1) { ISSUE_CHUNK(1); }
    CP_COMMIT();

    for (int ch = 0; ch < CH; ch++) {
        CP_WAIT1();            // groups <= ch complete -> chunk ch resident
        __syncthreads();
        if (ch + NSTAGE - 1 < CH) { ISSUE_CHUNK(ch + NSTAGE - 1); }
        CP_COMMIT();           // unconditional: keeps group<->chunk indexing exact

        uint32_t abase = sb + (ch % NSTAGE) * STAGE_BYTES;
        uint32_t bbase = abase + 16384;
        #pragma unroll
        for (int ks = 0; ks < 4; ks++) {
            uint32_t af[2][4];
            #pragma unroll
            for (int mt = 0; mt < 2; mt++) {
                int r = arow + mt * 16;
                uint32_t addr = abase + SWZ((uint32_t)(r * 128 + (2 * ks + achunkoff) * 16));
                LDSM_X4(af[mt][0], af[mt][1], af[mt][2], af[mt][3], addr);
                if (ROUND_A) {
                    #pragma unroll
                    for (int q = 0; q < 4; q++) af[mt][q] = tf32r(af[mt][q]);
                }
            }
            uint32_t bf[4][4];
            #pragma unroll
            for (int jp = 0; jp < 4; jp++) {
                int r = brow + jp * 16;
                uint32_t addr = bbase + SWZ((uint32_t)(r * 128 + (2 * ks + bchunkoff) * 16));
                LDSM_X4(bf[jp][0], bf[jp][1], bf[jp][2], bf[jp][3], addr);
            }
            #pragma unroll
            for (int mt = 0; mt < 2; mt++)
                #pragma unroll
                for (int j = 0; j < 8; j++)
                    MMA_TF32(acc[mt][j], af[mt][0], af[mt][1], af[mt][2], af[mt][3],
                             bf[j >> 1][(j & 1) * 2], bf[j >> 1][(j & 1) * 2 + 1]);
        }
    }

    #pragma unroll
    for (int mt = 0; mt < 2; mt++) {
        int r0 = rowBase + warpM * 32 + mt * 16 + (lane >> 2);
        int r1 = r0 + 8;
        float s0 = (rowscale && r0 < M) ? rowscale[r0] : 1.f;
        float s1 = (rowscale && r1 < M) ? rowscale[r1] : 1.f;
        #pragma unroll
        for (int j = 0; j < 8; j++) {
            int gc = colBase + warpN * 64 + j * 8 + (lane & 3) * 2;
            float2 v0 = make_float2(acc[mt][j][0] * s0, acc[mt][j][1] * s0);
            float2 v1 = make_float2(acc[mt][j][2] * s1, acc[mt][j][3] * s1);
            if (bias) {
                float2 bb = *(const float2*)&bias[gc];
                v0.x += bb.x; v0.y += bb.y;
                v1.x += bb.x; v1.y += bb.y;
            }
            if (r0 < M) {
                if (emb) {
                    float2 e0 = *(const float2*)&emb[(size_t)r0 * 256 + gc];
                    v0.x += e0.x; v0.y += e0.y;
                }
                if (ROUND_OUT) { v0.x = tf32f(v0.x); v0.y = tf32f(v0.y); }
                *(float2*)&C[(size_t)r0 * 256 + gc] = v0;
            }
            if (r1 < M) {
                if (emb) {
                    float2 e1 = *(const float2*)&emb[(size_t)r1 * 256 + gc];
                    v1.x += e1.x; v1.y += e1.y;
                }
                if (ROUND_OUT) { v1.x = tf32f(v1.x); v1.y = tf32f(v1.y); }
                *(float2*)&C[(size_t)r1 * 256 + gc] = v1;
            }
        }
    }
    #undef ISSUE_CHUNK
}

// conv GEMM: A = g_x (pre-rounded), out = g_h raw fp32 scaled by dinv
__global__ __launch_bounds__(256, 2) void gemm_conv(const float* __restrict__ A,
                                                    const float* __restrict__ Bt, int ldb,
                                                    const float* __restrict__ rowscale,
                                                    float* __restrict__ C, int M, int K) {
    extern __shared__ char smem[];
    gemm_body<false, false>(A, Bt, ldb, nullptr, nullptr, rowscale, C, M, K,
                            blockIdx.x, blockIdx.y, smem_u32(smem));
}

// input transform (dual U/P): A = raw features (round frags), out rounded (feeds conv1)
__global__ __launch_bounds__(256, 2) void gemm_dual_in(
    const float* __restrict__ A0, const float* __restrict__ B0,
    const float* __restrict__ bias0, const float* __restrict__ emb0,
    float* __restrict__ C0, int M0,
    const float* __restrict__ A1, const float* __restrict__ B1,
    const float* __restrict__ bias1, const float* __restrict__ emb1,
    float* __restrict__ C1, int M1,
    int ldb, int K, int split) {
    extern __shared__ char smem[];
    uint32_t sb = smem_u32(smem);
    if ((int)blockIdx.x < split)
        gemm_body<true, true>(A0, B0, ldb, bias0, emb0, nullptr, C0, M0, K,
                              blockIdx.x, blockIdx.y, sb);
    else
        gemm_body<true, true>(A1, B1, ldb, bias1, emb1, nullptr, C1, M1, K,
                              blockIdx.x - split, blockIdx.y, sb);
}

// MLP partials (dual U/P): A = g_x (pre-rounded), out raw fp32 (feeds edge_pred)
__global__ __launch_bounds__(256, 2) void gemm_dual_mlp(
    const float* __restrict__ A0, const float* __restrict__ B0,
    float* __restrict__ C0, int M0,
    const float* __restrict__ A1, const float* __restrict__ B1,
    float* __restrict__ C1, int M1,
    int ldb, int K, int split) {
    extern __shared__ char smem[];
    uint32_t sb = smem_u32(smem);
    if ((int)blockIdx.x < split)
        gemm_body<false, false>(A0, B0, ldb, nullptr, nullptr, nullptr, C0, M0, K,
                                blockIdx.x, blockIdx.y, sb);
    else
        gemm_body<false, false>(A1, B1, ldb, nullptr, nullptr, nullptr, C1, M1, K,
                                blockIdx.x - split, blockIdx.y, sb);
}

// ================= fused GCN aggregation (CSR row-sum of h_scaled) =================
// g_h holds h_scaled = h * dinv[row].  out[n] = tf32((sum+self)*dinv[n] + b)  -> g_x
__global__ void k_gather(const float* __restrict__ b, int relu) {
    int i = blockIdx.x * blockDim.x + threadIdx.x;
    if (i >= NN * 64) return;
    int n = i >> 6;
    int c = (i & 63) << 2;
    float di = g_dinv[n];
    float4 acc = *(const float4*)&g_h[(size_t)n * D + c];   // self (scaled)
    int s0 = g_off[n];
    int s1 = s0 + g_deg[n];
    int j = s0;
    for (; j + 1 < s1; j += 2) {
        int a0 = g_adj[j];
        int a1 = g_adj[j + 1];
        float4 h0 = *(const float4*)&g_h[(size_t)a0 * D + c];
        float4 h1 = *(const float4*)&g_h[(size_t)a1 * D + c];
        acc.x += h0.x + h1.x; acc.y += h0.y + h1.y;
        acc.z += h0.z + h1.z; acc.w += h0.w + h1.w;
    }
    if (j < s1) {
        int a = g_adj[j];
        float4 hv = *(const float4*)&g_h[(size_t)a * D + c];
        acc.x += hv.x; acc.y += hv.y; acc.z += hv.z; acc.w += hv.w;
    }
    float4 bb = *(const float4*)&b[c];
    acc.x = acc.x * di + bb.x; acc.y = acc.y * di + bb.y;
    acc.z = acc.z * di + bb.z; acc.w = acc.w * di + bb.w;
    if (relu) {
        acc.x = fmaxf(acc.x, 0.f); acc.y = fmaxf(acc.y, 0.f);
        acc.z = fmaxf(acc.z, 0.f); acc.w = fmaxf(acc.w, 0.f);
    }
    // pre-round for the consuming GEMM's A operand (single rounding, same result)
    acc.x = tf32f(acc.x); acc.y = tf32f(acc.y);
    acc.z = tf32f(acc.z); acc.w = tf32f(acc.w);
    *(float4*)&g_x[(size_t)n * D + c] = acc;
}

// ================= per-edge MLP, user-ordered (warp per user) =================
__global__ void k_edge_pred_user(const float* __restrict__ m1b,
                                 const float* __restrict__ m2W,
                                 const float* __restrict__ m2b,
                                 float* __restrict__ out) {
    int gid = blockIdx.x * blockDim.x + threadIdx.x;
    int u = gid >> 5;
    int lane = gid & 31;
    if (u >= NU) return;
    int dg = g_deg[u];
    if (dg == 0) return;
    int s0 = g_off[u];

    const float4* hu4 = (const float4*)&g_h[(size_t)u * D];
    float4 a0 = hu4[lane];
    float4 a1 = hu4[lane + 32];
    float4 bb0 = ((const float4*)m1b)[lane];
    float4 bb1 = ((const float4*)m1b)[lane + 32];
    a0.x += bb0.x; a0.y += bb0.y; a0.z += bb0.z; a0.w += bb0.w;
    a1.x += bb1.x; a1.y += bb1.y; a1.z += bb1.z; a1.w += bb1.w;
    float4 w0 = ((const float4*)m2W)[lane];
    float4 w1 = ((const float4*)m2W)[lane + 32];
    float m2bb = m2b[0];

    for (int j = s0; j < s0 + dg; j++) {
        int p = g_adj[j];
        int e = g_aid[j];
        const float4* hp4 = (const float4*)&g_h[(size_t)p * D];
        float4 b0 = hp4[lane];
        float4 b1 = hp4[lane + 32];
        float s = fmaxf(a0.x + b0.x, 0.f) * w0.x
                + fmaxf(a0.y + b0.y, 0.f) * w0.y
                + fmaxf(a0.z + b0.z, 0.f) * w0.z
                + fmaxf(a0.w + b0.w, 0.f) * w0.w
                + fmaxf(a1.x + b1.x, 0.f) * w1.x
                + fmaxf(a1.y + b1.y, 0.f) * w1.y
                + fmaxf(a1.z + b1.z, 0.f) * w1.z
                + fmaxf(a1.w + b1.w, 0.f) * w1.w;
        #pragma unroll
        for (int o = 16; o; o >>= 1) s += __shfl_down_sync(0xFFFFFFFFu, s, o);
        if (lane == 0) out[e] = s + m2bb;
    }
}

// ================= launch =================
extern "C" void kernel_launch(void* const* d_in, const int* in_sizes, int n_in,
                              void* d_out, int out_size) {
    const int*   ei   = (const int*)d_in[0];
    const float* uf   = (const float*)d_in[1];
    const float* pf   = (const float*)d_in[2];
    const float* uemb = (const float*)d_in[3];
    const float* pemb = (const float*)d_in[4];
    const float* uW   = (const float*)d_in[5];
    const float* ub   = (const float*)d_in[6];
    const float* pW   = (const float*)d_in[7];
    const float* pb   = (const float*)d_in[8];
    const float* c1W  = (const float*)d_in[9];
    const float* c1b  = (const float*)d_in[10];
    const float* c2W  = (const float*)d_in[11];
    const float* c2b  = (const float*)d_in[12];
    const float* m1W  = (const float*)d_in[13];
    const float* m1b  = (const float*)d_in[14];
    const float* m2W  = (const float*)d_in[15];
    const float* m2b  = (const float*)d_in[16];
    float* preds = (float*)d_out;

    float* xp;  float* hp;  float* wt;  float* dv;  int* degp; int* totp;
    cudaGetSymbolAddress((void**)&xp, g_x);
    cudaGetSymbolAddress((void**)&hp, g_h);
    cudaGetSymbolAddress((void**)&wt, g_wt);
    cudaGetSymbolAddress((void**)&dv, g_dinv);
    cudaGetSymbolAddress((void**)&degp, g_deg);
    cudaGetSymbolAddress((void**)&totp, g_total);

    static cudaStream_t s2 = nullptr;
    static cudaEvent_t evFork = nullptr, evJoin = nullptr;
    static bool attrSet = false;
    if (!s2) {
        cudaStreamCreateWithFlags(&s2, cudaStreamNonBlocking);
        cudaEventCreateWithFlags(&evFork, cudaEventDisableTiming);
        cudaEventCreateWithFlags(&evJoin, cudaEventDisableTiming);
    }
    if (!attrSet) {
        cudaFuncSetAttribute(gemm_conv,     cudaFuncAttributeMaxDynamicSharedMemorySize, GEMM_SMEM);
        cudaFuncSetAttribute(gemm_dual_in,  cudaFuncAttributeMaxDynamicSharedMemorySize, GEMM_SMEM);
        cudaFuncSetAttribute(gemm_dual_mlp, cudaFuncAttributeMaxDynamicSharedMemorySize, GEMM_SMEM);
        attrSet = true;
    }

    // ---- fork: CSR build on s2 ----
    cudaEventRecord(evFork, 0);
    cudaStreamWaitEvent(s2, evFork, 0);
    cudaMemsetAsync(degp, 0, NN * sizeof(int), s2);
    cudaMemsetAsync(totp, 0, sizeof(int), s2);
    k_degree<<<(NE + 255) / 256, 256, 0, s2>>>(ei);
    k_offsets<<<(NN + 255) / 256, 256, 0, s2>>>();
    k_fill<<<(NE + 255) / 256, 256, 0, s2>>>(ei);
    cudaEventRecord(evJoin, s2);

    // ---- main stream: transposes ----
    dim3 tb(32, 8);
    k_transpose<<<dim3(8, 4),  tb>>>(uW,  wt + WT_U,  128, 256);
    k_transpose<<<dim3(8, 4),  tb>>>(pW,  wt + WT_P,  128, 256);
    k_transpose<<<dim3(8, 8),  tb>>>(c1W, wt + WT_C1, 256, 256);
    k_transpose<<<dim3(8, 8),  tb>>>(c2W, wt + WT_C2, 256, 256);
    k_transpose<<<dim3(8, 16), tb>>>(m1W, wt + WT_M1, 512, 256);

    const int gU = (NU + 127) / 128;
    const int gP = (NP + 127) / 128;
    const int gN = (NN + 127) / 128;
    const int nElem = (NN * 64 + 255) / 256;

    // input transforms (merged U+P): x = tf32(feats @ W + b + emb)
    gemm_dual_in<<<dim3(gU + gP, 2), 256, GEMM_SMEM>>>(
        uf, wt + WT_U, ub, uemb, xp, NU,
        pf, wt + WT_P, pb, pemb, xp + (size_t)NU * D, NP,
        128, 128, gU);

    // conv1 (relu): GEMM writes h*dinv ; epilogue + gather need dinv/CSR from s2
    cudaStreamWaitEvent(0, evJoin, 0);
    gemm_conv<<<dim3(gN, 2), 256, GEMM_SMEM>>>(xp, wt + WT_C1, 256, dv, hp, NN, 256);
    k_gather<<<nElem, 256>>>(c1b, 1);

    // conv2 (no relu)
    gemm_conv<<<dim3(gN, 2), 256, GEMM_SMEM>>>(xp, wt + WT_C2, 256, dv, hp, NN, 256);
    k_gather<<<nElem, 256>>>(c2b, 0);

    // MLP factored through nodes (merged U+P)
    gemm_dual_mlp<<<dim3(gU + gP, 2), 256, GEMM_SMEM>>>(
        xp, wt + WT_M1, hp, NU,
        xp + (size_t)NU * D, wt + WT_M1 + 256, hp + (size_t)NU * D, NP,
        512, 256, gU);

    // per-edge scoring, user-ordered
    k_edge_pred_user<<<(NU * 32 + 255) / 256, 256>>>(m1b, m2W, m2b, preds);
}